// round 1
// baseline (speedup 1.0000x reference)
#include <cuda_runtime.h>
#include <math.h>

#define MTOT 32768   // B*S
#define DDIM 1024
#define SSEQ 4096
#define BB   8
#define HH   16
#define DK   64

#define BM 128
#define BN 128
#define BK 16
#define TM 8
#define TN 8

// Scratch (no cudaMalloc allowed): 4 x 134 MB + small KV state
__device__ float g_Q[MTOT * DDIM];
__device__ float g_K[MTOT * DDIM];
__device__ float g_V[MTOT * DDIM];
__device__ float g_A[MTOT * DDIM];
__device__ float g_KV[BB * HH * DK * DK];
__device__ float g_Ksum[BB * HH * DK];

// C[m,n] = sum_k A[m,k] * W[n,k] + bias[n]; optional phi = elu(x)+1
__global__ __launch_bounds__(256)
void sgemm_wt(const float* __restrict__ A, const float* __restrict__ W,
              const float* __restrict__ bias, float* __restrict__ C,
              int K, int N, int do_phi)
{
    __shared__ float As[BK][BM];
    __shared__ float Bs[BK][BN];

    const int tid = threadIdx.x;
    const size_t bm = (size_t)blockIdx.y * BM;
    const size_t bn = (size_t)blockIdx.x * BN;

    const int lr = tid >> 2;   // 0..63 : tile row (two rows per thread, +64)
    const int lc = tid & 3;    // 0..3  : float4 column within BK=16

    const int tx = tid & 15;   // output col group
    const int ty = tid >> 4;   // output row group

    float acc[TM][TN];
#pragma unroll
    for (int i = 0; i < TM; i++)
#pragma unroll
        for (int j = 0; j < TN; j++) acc[i][j] = 0.f;

    const float* Ab = A + bm * (size_t)K;
    const float* Wb = W + bn * (size_t)K;

    for (int k0 = 0; k0 < K; k0 += BK) {
#pragma unroll
        for (int i = 0; i < 2; i++) {
            int r = lr + i * 64;
            float4 va = *(const float4*)(Ab + (size_t)r * K + k0 + lc * 4);
            As[lc * 4 + 0][r] = va.x;
            As[lc * 4 + 1][r] = va.y;
            As[lc * 4 + 2][r] = va.z;
            As[lc * 4 + 3][r] = va.w;
            float4 vw = *(const float4*)(Wb + (size_t)r * K + k0 + lc * 4);
            Bs[lc * 4 + 0][r] = vw.x;
            Bs[lc * 4 + 1][r] = vw.y;
            Bs[lc * 4 + 2][r] = vw.z;
            Bs[lc * 4 + 3][r] = vw.w;
        }
        __syncthreads();

#pragma unroll
        for (int k = 0; k < BK; k++) {
            float regM[TM], regN[TN];
#pragma unroll
            for (int i = 0; i < TM; i++) regM[i] = As[k][ty * TM + i];
#pragma unroll
            for (int j = 0; j < TN; j++) regN[j] = Bs[k][tx * TN + j];
#pragma unroll
            for (int i = 0; i < TM; i++)
#pragma unroll
                for (int j = 0; j < TN; j++) acc[i][j] += regM[i] * regN[j];
        }
        __syncthreads();
    }

#pragma unroll
    for (int i = 0; i < TM; i++) {
        size_t row = bm + ty * TM + i;
#pragma unroll
        for (int j = 0; j < TN; j++) {
            int col = (int)bn + tx * TN + j;
            float v = acc[i][j] + bias[col];
            if (do_phi) v = (v > 0.f) ? (v + 1.f) : expf(v);
            C[row * (size_t)N + col] = v;
        }
    }
}

// Per (b,h): KV[d][e] = sum_s K[s,d]*V[s,e];  Ksum[d] = sum_s K[s,d]
__global__ __launch_bounds__(256)
void kv_kernel()
{
    const int bh = blockIdx.x;            // 0..127
    const int b = bh >> 4, h = bh & 15;

    const float* Kp = g_K + (size_t)b * SSEQ * DDIM + h * DK;
    const float* Vp = g_V + (size_t)b * SSEQ * DDIM + h * DK;

    __shared__ float Ks[32][DK];
    __shared__ float Vs[32][DK];

    const int tid = threadIdx.x;
    const int r  = tid >> 4;      // 0..15 (load rows r, r+16)
    const int c4 = tid & 15;      // float4 col 0..15

    const int tx = tid & 15, ty = tid >> 4;
    const int d0 = ty * 4, e0 = tx * 4;

    float acc[4][4];
#pragma unroll
    for (int i = 0; i < 4; i++)
#pragma unroll
        for (int j = 0; j < 4; j++) acc[i][j] = 0.f;
    float ks = 0.f;

    for (int s0 = 0; s0 < SSEQ; s0 += 32) {
        const float* kb = Kp + (size_t)s0 * DDIM;
        const float* vb = Vp + (size_t)s0 * DDIM;
        *(float4*)&Ks[r][c4 * 4]      = *(const float4*)(kb + (size_t)r * DDIM + c4 * 4);
        *(float4*)&Ks[r + 16][c4 * 4] = *(const float4*)(kb + (size_t)(r + 16) * DDIM + c4 * 4);
        *(float4*)&Vs[r][c4 * 4]      = *(const float4*)(vb + (size_t)r * DDIM + c4 * 4);
        *(float4*)&Vs[r + 16][c4 * 4] = *(const float4*)(vb + (size_t)(r + 16) * DDIM + c4 * 4);
        __syncthreads();

#pragma unroll
        for (int s = 0; s < 32; s++) {
            float4 kk = *(const float4*)&Ks[s][d0];
            float4 vv = *(const float4*)&Vs[s][e0];
            float kr[4] = {kk.x, kk.y, kk.z, kk.w};
            float vr[4] = {vv.x, vv.y, vv.z, vv.w};
#pragma unroll
            for (int i = 0; i < 4; i++)
#pragma unroll
                for (int j = 0; j < 4; j++) acc[i][j] += kr[i] * vr[j];
        }
        if (tid < DK) {
#pragma unroll
            for (int s = 0; s < 32; s++) ks += Ks[s][tid];
        }
        __syncthreads();
    }

    float* out = g_KV + (size_t)bh * DK * DK;
#pragma unroll
    for (int i = 0; i < 4; i++)
#pragma unroll
        for (int j = 0; j < 4; j++) out[(d0 + i) * DK + e0 + j] = acc[i][j];
    if (tid < DK) g_Ksum[bh * DK + tid] = ks;
}

// out[s,e] = (sum_d Q[s,d]*KV[d,e]) / (sum_d Q[s,d]*Ksum[d] + eps)
__global__ __launch_bounds__(256)
void attn_kernel()
{
    const int bh = blockIdx.y;
    const int b = bh >> 4, h = bh & 15;
    const int s_base = blockIdx.x * 128;

    __shared__ float KVs[DK][DK];
    __shared__ float Ksm[DK];
    __shared__ float Qs[32][DK];

    const int tid = threadIdx.x;

    const float* kvp = g_KV + (size_t)bh * DK * DK;
    for (int i = tid; i < DK * DK / 4; i += 256)
        ((float4*)KVs)[i] = ((const float4*)kvp)[i];
    if (tid < DK) Ksm[tid] = g_Ksum[bh * DK + tid];
    __syncthreads();

    const float* Qp = g_Q + (size_t)b * SSEQ * DDIM + h * DK;
    float* Op       = g_A + (size_t)b * SSEQ * DDIM + h * DK;

    const int r  = tid >> 4;   // load rows
    const int c4 = tid & 15;
    const int sl = tid >> 3;   // 0..31 : local s row
    const int g  = tid & 7;    // output col group
    const int e0 = g * 8;

    for (int c = 0; c < 4; c++) {
        int s0 = s_base + c * 32;
        *(float4*)&Qs[r][c4 * 4]      = *(const float4*)(Qp + (size_t)(s0 + r) * DDIM + c4 * 4);
        *(float4*)&Qs[r + 16][c4 * 4] = *(const float4*)(Qp + (size_t)(s0 + r + 16) * DDIM + c4 * 4);
        __syncthreads();

        float acc[8];
#pragma unroll
        for (int j = 0; j < 8; j++) acc[j] = 0.f;
        float z = 0.f;
#pragma unroll
        for (int d = 0; d < DK; d++) {
            float q = Qs[sl][d];
            z += q * Ksm[d];
#pragma unroll
            for (int j = 0; j < 8; j++) acc[j] += q * KVs[d][e0 + j];
        }
        float invz = 1.f / (z + 1e-6f);
        float* op = Op + (size_t)(s0 + sl) * DDIM + e0;
#pragma unroll
        for (int j = 0; j < 8; j++) op[j] = acc[j] * invz;
        __syncthreads();
    }
}

extern "C" void kernel_launch(void* const* d_in, const int* in_sizes, int n_in,
                              void* d_out, int out_size)
{
    const float* x  = (const float*)d_in[0];
    const float* Wq = (const float*)d_in[1];
    const float* bq = (const float*)d_in[2];
    const float* Wk = (const float*)d_in[3];
    const float* bk = (const float*)d_in[4];
    const float* Wv = (const float*)d_in[5];
    const float* bv = (const float*)d_in[6];
    const float* Wo = (const float*)d_in[7];
    const float* bo = (const float*)d_in[8];

    float *Qb, *Kb, *Vb, *Ab;
    cudaGetSymbolAddress((void**)&Qb, g_Q);
    cudaGetSymbolAddress((void**)&Kb, g_K);
    cudaGetSymbolAddress((void**)&Vb, g_V);
    cudaGetSymbolAddress((void**)&Ab, g_A);

    dim3 grid(DDIM / BN, MTOT / BM);

    sgemm_wt<<<grid, 256>>>(x, Wq, bq, Qb, DDIM, DDIM, 1);
    sgemm_wt<<<grid, 256>>>(x, Wk, bk, Kb, DDIM, DDIM, 1);
    sgemm_wt<<<grid, 256>>>(x, Wv, bv, Vb, DDIM, DDIM, 0);

    kv_kernel<<<BB * HH, 256>>>();
    attn_kernel<<<dim3(SSEQ / 128, BB * HH), 256>>>();

    sgemm_wt<<<grid, 256>>>(Ab, Wo, bo, (float*)d_out, DDIM, DDIM, 0);
}

// round 4
// speedup vs baseline: 2.9352x; 2.9352x over previous
#include <cuda_runtime.h>
#include <cstdint>
#include <math.h>

#define MTOT 32768   // B*S
#define DDIM 1024
#define SSEQ 4096
#define BB   8
#define HH   16
#define DK   64

// ---------------- scratch (no cudaMalloc allowed) ----------------
__device__ float g_Q[MTOT * DDIM];
__device__ float g_K[MTOT * DDIM];
__device__ float g_V[MTOT * DDIM];
__device__ float g_A[MTOT * DDIM];
__device__ float g_KVp[4][BB * HH * DK * DK];
__device__ float g_Ksp[4][BB * HH * DK];
__device__ float g_KV[BB * HH * DK * DK];
__device__ float g_Ksum[BB * HH * DK];

// ---------------- tf32 mma.sync GEMM ----------------
// C[m,n] = sum_k A[m,k] * W[n,k] + bias[n], optional phi = elu+1
#define BMg 128
#define BNg 128
#define BKg 32
#define KPAD 36          // 32 + 4 pad floats: conflict-free fragment LDS
#define NSTG 3
#define STAGE_F (128 * KPAD)
#define GEMM_SMEM (2 * NSTG * STAGE_F * 4)   // 110592 bytes

__device__ __forceinline__ uint32_t smem_u32(const void* p) {
    uint32_t a;
    asm("{ .reg .u64 t; cvta.to.shared.u64 t, %1; cvt.u32.u64 %0, t; }" : "=r"(a) : "l"(p));
    return a;
}

__device__ __forceinline__ void cp16(uint32_t dst, const void* src) {
    asm volatile("cp.async.cg.shared.global [%0], [%1], 16;" :: "r"(dst), "l"(src));
}

__device__ __forceinline__ uint32_t to_tf32(float f) {
    uint32_t r;
    asm("cvt.rna.tf32.f32 %0, %1;" : "=r"(r) : "f"(f));
    return r;
}

__device__ __forceinline__ void mma_tf32(float& d0, float& d1, float& d2, float& d3,
                                         uint32_t a0, uint32_t a1, uint32_t a2, uint32_t a3,
                                         uint32_t b0, uint32_t b1) {
    asm volatile(
        "mma.sync.aligned.m16n8k8.row.col.f32.tf32.tf32.f32 "
        "{%0,%1,%2,%3},{%4,%5,%6,%7},{%8,%9},{%0,%1,%2,%3};"
        : "+f"(d0), "+f"(d1), "+f"(d2), "+f"(d3)
        : "r"(a0), "r"(a1), "r"(a2), "r"(a3), "r"(b0), "r"(b1));
}

__global__ void __launch_bounds__(256, 1) gemm_mma(
    const float* __restrict__ A, const float* __restrict__ W,
    const float* __restrict__ bias, float* __restrict__ C, int do_phi)
{
    extern __shared__ float sm[];
    float* As = sm;                       // [NSTG][128][KPAD]
    float* Bs = sm + NSTG * STAGE_F;
    const uint32_t as_u = smem_u32(As), bs_u = smem_u32(Bs);

    const int tid = threadIdx.x;
    const int wid = tid >> 5, lane = tid & 31;
    const int tr = lane >> 2, tc = lane & 3;
    const int m0 = blockIdx.y * BMg, n0 = blockIdx.x * BNg;
    const int wm = (wid & 3) * 32, wn = (wid >> 2) * 64;

    float acc[2][8][4];
#pragma unroll
    for (int i = 0; i < 2; i++)
#pragma unroll
        for (int j = 0; j < 8; j++)
#pragma unroll
            for (int q = 0; q < 4; q++) acc[i][j][q] = 0.f;

    // stage loader: 1024 float4 per operand per stage; 4 per thread
    auto load_stage = [&](int s, int k0) {
#pragma unroll
        for (int i = 0; i < 4; i++) {
            int idx = tid + i * 256;
            int r = idx >> 3, c = idx & 7;
            cp16(as_u + (uint32_t)((s * STAGE_F + r * KPAD + c * 4) * 4),
                 &A[(size_t)(m0 + r) * DDIM + k0 + c * 4]);
            cp16(bs_u + (uint32_t)((s * STAGE_F + r * KPAD + c * 4) * 4),
                 &W[(size_t)(n0 + r) * DDIM + k0 + c * 4]);
        }
        asm volatile("cp.async.commit_group;" ::: "memory");
    };

#pragma unroll
    for (int s = 0; s < NSTG; s++) load_stage(s, s * BKg);

    const int NCHUNK = DDIM / BKg;  // 32
#pragma unroll 1
    for (int ck = 0; ck < NCHUNK; ck++) {
        const int s = ck % NSTG;
        asm volatile("cp.async.wait_group %0;" :: "n"(NSTG - 1) : "memory");
        __syncthreads();

        const float* aw = As + s * STAGE_F + wm * KPAD;
        const float* bw = Bs + s * STAGE_F + wn * KPAD;
#pragma unroll
        for (int ks = 0; ks < 4; ks++) {
            const int kk = ks * 8 + tc;
            uint32_t af[2][4];
#pragma unroll
            for (int mt = 0; mt < 2; mt++) {
                const float* p = aw + (mt * 16 + tr) * KPAD + kk;
                af[mt][0] = to_tf32(p[0]);
                af[mt][1] = to_tf32(p[8 * KPAD]);
                af[mt][2] = to_tf32(p[4]);
                af[mt][3] = to_tf32(p[8 * KPAD + 4]);
            }
            uint32_t bf[8][2];
#pragma unroll
            for (int nt = 0; nt < 8; nt++) {
                const float* p = bw + (nt * 8 + tr) * KPAD + kk;
                bf[nt][0] = to_tf32(p[0]);
                bf[nt][1] = to_tf32(p[4]);
            }
#pragma unroll
            for (int mt = 0; mt < 2; mt++)
#pragma unroll
                for (int nt = 0; nt < 8; nt++)
                    mma_tf32(acc[mt][nt][0], acc[mt][nt][1], acc[mt][nt][2], acc[mt][nt][3],
                             af[mt][0], af[mt][1], af[mt][2], af[mt][3],
                             bf[nt][0], bf[nt][1]);
        }
        __syncthreads();
        if (ck + NSTG < NCHUNK) load_stage(s, (ck + NSTG) * BKg);
    }

    // epilogue: bias (+phi), direct float2 stores (full 32B sectors)
#pragma unroll
    for (int mt = 0; mt < 2; mt++) {
        const int row = m0 + wm + mt * 16 + tr;
#pragma unroll
        for (int nt = 0; nt < 8; nt++) {
            const int col = n0 + wn + nt * 8 + tc * 2;
            const float bv0 = __ldg(&bias[col]), bv1 = __ldg(&bias[col + 1]);
            float v0 = acc[mt][nt][0] + bv0;
            float v1 = acc[mt][nt][1] + bv1;
            float v2 = acc[mt][nt][2] + bv0;
            float v3 = acc[mt][nt][3] + bv1;
            if (do_phi) {
                v0 = (v0 > 0.f) ? (v0 + 1.f) : __expf(v0);
                v1 = (v1 > 0.f) ? (v1 + 1.f) : __expf(v1);
                v2 = (v2 > 0.f) ? (v2 + 1.f) : __expf(v2);
                v3 = (v3 > 0.f) ? (v3 + 1.f) : __expf(v3);
            }
            *(float2*)&C[(size_t)row * DDIM + col]       = make_float2(v0, v1);
            *(float2*)&C[(size_t)(row + 8) * DDIM + col] = make_float2(v2, v3);
        }
    }
}

// ---------------- KV = K^T V per (b,h), split over S into 4 partials ----------------
__global__ __launch_bounds__(256)
void kv_part_kernel()
{
    const int bh = blockIdx.x;            // 0..127
    const int part = blockIdx.y;          // 0..3
    const int b = bh >> 4, h = bh & 15;
    const int sbeg = part * (SSEQ / 4), send = sbeg + (SSEQ / 4);

    const float* Kp = g_K + (size_t)b * SSEQ * DDIM + h * DK;
    const float* Vp = g_V + (size_t)b * SSEQ * DDIM + h * DK;

    __shared__ float Ks[32][DK];
    __shared__ float Vs[32][DK];

    const int tid = threadIdx.x;
    const int r  = tid >> 4;
    const int c4 = tid & 15;
    const int tx = tid & 15, ty = tid >> 4;
    const int d0 = ty * 4, e0 = tx * 4;

    float acc[4][4];
#pragma unroll
    for (int i = 0; i < 4; i++)
#pragma unroll
        for (int j = 0; j < 4; j++) acc[i][j] = 0.f;
    float ks = 0.f;

    for (int s0 = sbeg; s0 < send; s0 += 32) {
        const float* kb = Kp + (size_t)s0 * DDIM;
        const float* vb = Vp + (size_t)s0 * DDIM;
        *(float4*)&Ks[r][c4 * 4]      = *(const float4*)(kb + (size_t)r * DDIM + c4 * 4);
        *(float4*)&Ks[r + 16][c4 * 4] = *(const float4*)(kb + (size_t)(r + 16) * DDIM + c4 * 4);
        *(float4*)&Vs[r][c4 * 4]      = *(const float4*)(vb + (size_t)r * DDIM + c4 * 4);
        *(float4*)&Vs[r + 16][c4 * 4] = *(const float4*)(vb + (size_t)(r + 16) * DDIM + c4 * 4);
        __syncthreads();

#pragma unroll
        for (int s = 0; s < 32; s++) {
            float4 kk = *(const float4*)&Ks[s][d0];
            float4 vv = *(const float4*)&Vs[s][e0];
            float kr[4] = {kk.x, kk.y, kk.z, kk.w};
            float vr[4] = {vv.x, vv.y, vv.z, vv.w};
#pragma unroll
            for (int i = 0; i < 4; i++)
#pragma unroll
                for (int j = 0; j < 4; j++) acc[i][j] += kr[i] * vr[j];
        }
        if (tid < DK) {
#pragma unroll
            for (int s = 0; s < 32; s++) ks += Ks[s][tid];
        }
        __syncthreads();
    }

    float* out = g_KVp[part] + (size_t)bh * DK * DK;
#pragma unroll
    for (int i = 0; i < 4; i++)
#pragma unroll
        for (int j = 0; j < 4; j++) out[(d0 + i) * DK + e0 + j] = acc[i][j];
    if (tid < DK) g_Ksp[part][bh * DK + tid] = ks;
}

__global__ __launch_bounds__(256)
void kv_reduce_kernel()
{
    const int bh = blockIdx.x;
    const int tid = threadIdx.x;
    const size_t base = (size_t)bh * DK * DK;
    for (int i = tid; i < DK * DK; i += 256) {
        float s = g_KVp[0][base + i] + g_KVp[1][base + i]
                + g_KVp[2][base + i] + g_KVp[3][base + i];
        g_KV[base + i] = s;
    }
    if (tid < DK) {
        const int o = bh * DK + tid;
        g_Ksum[o] = g_Ksp[0][o] + g_Ksp[1][o] + g_Ksp[2][o] + g_Ksp[3][o];
    }
}

// ---------------- out = (Q·KV) / (Q·Ksum + eps) ----------------
__global__ __launch_bounds__(256)
void attn_kernel()
{
    const int bh = blockIdx.y;
    const int b = bh >> 4, h = bh & 15;
    const int s_base = blockIdx.x * 128;

    __shared__ float KVs[DK][DK];
    __shared__ float Ksm[DK];
    __shared__ float Qs[32][DK];

    const int tid = threadIdx.x;

    const float* kvp = g_KV + (size_t)bh * DK * DK;
    for (int i = tid; i < DK * DK / 4; i += 256)
        ((float4*)KVs)[i] = ((const float4*)kvp)[i];
    if (tid < DK) Ksm[tid] = g_Ksum[bh * DK + tid];
    __syncthreads();

    const float* Qp = g_Q + (size_t)b * SSEQ * DDIM + h * DK;
    float* Op       = g_A + (size_t)b * SSEQ * DDIM + h * DK;

    const int r  = tid >> 4;
    const int c4 = tid & 15;
    const int sl = tid >> 3;
    const int g  = tid & 7;
    const int e0 = g * 8;

    for (int c = 0; c < 4; c++) {
        int s0 = s_base + c * 32;
        *(float4*)&Qs[r][c4 * 4]      = *(const float4*)(Qp + (size_t)(s0 + r) * DDIM + c4 * 4);
        *(float4*)&Qs[r + 16][c4 * 4] = *(const float4*)(Qp + (size_t)(s0 + r + 16) * DDIM + c4 * 4);
        __syncthreads();

        float acc[8];
#pragma unroll
        for (int j = 0; j < 8; j++) acc[j] = 0.f;
        float z = 0.f;
#pragma unroll
        for (int d = 0; d < DK; d++) {
            float q = Qs[sl][d];
            z += q * Ksm[d];
#pragma unroll
            for (int j = 0; j < 8; j++) acc[j] += q * KVs[d][e0 + j];
        }
        float invz = 1.f / (z + 1e-6f);
        float* op = Op + (size_t)(s0 + sl) * DDIM + e0;
#pragma unroll
        for (int j = 0; j < 8; j++) op[j] = acc[j] * invz;
        __syncthreads();
    }
}

// ---------------- host ----------------
extern "C" void kernel_launch(void* const* d_in, const int* in_sizes, int n_in,
                              void* d_out, int out_size)
{
    const float* x  = (const float*)d_in[0];
    const float* Wq = (const float*)d_in[1];
    const float* bq = (const float*)d_in[2];
    const float* Wk = (const float*)d_in[3];
    const float* bk = (const float*)d_in[4];
    const float* Wv = (const float*)d_in[5];
    const float* bv = (const float*)d_in[6];
    const float* Wo = (const float*)d_in[7];
    const float* bo = (const float*)d_in[8];

    float *Qb, *Kb, *Vb, *Ab;
    cudaGetSymbolAddress((void**)&Qb, g_Q);
    cudaGetSymbolAddress((void**)&Kb, g_K);
    cudaGetSymbolAddress((void**)&Vb, g_V);
    cudaGetSymbolAddress((void**)&Ab, g_A);

    cudaFuncSetAttribute(gemm_mma, cudaFuncAttributeMaxDynamicSharedMemorySize, GEMM_SMEM);

    dim3 gg(DDIM / BNg, MTOT / BMg);
    gemm_mma<<<gg, 256, GEMM_SMEM>>>(x, Wq, bq, Qb, 1);
    gemm_mma<<<gg, 256, GEMM_SMEM>>>(x, Wk, bk, Kb, 1);
    gemm_mma<<<gg, 256, GEMM_SMEM>>>(x, Wv, bv, Vb, 0);

    kv_part_kernel<<<dim3(BB * HH, 4), 256>>>();
    kv_reduce_kernel<<<BB * HH, 256>>>();
    attn_kernel<<<dim3(SSEQ / 128, BB * HH), 256>>>();

    gemm_mma<<<gg, 256, GEMM_SMEM>>>(Ab, Wo, bo, (float*)d_out, 0);
}

// round 6
// speedup vs baseline: 2.9771x; 1.0143x over previous
#include <cuda_runtime.h>
#include <cstdint>
#include <math.h>

#define MTOT 32768   // B*S
#define DDIM 1024
#define SSEQ 4096
#define BB   8
#define HH   16
#define DK   64
#define NPART 8

// ---------------- scratch (no cudaMalloc allowed) ----------------
__device__ float g_Q[MTOT * DDIM];
__device__ float g_K[MTOT * DDIM];
__device__ float g_V[MTOT * DDIM];
__device__ float g_A[MTOT * DDIM];
__device__ float g_KVp[NPART][BB * HH * DK * DK];
__device__ float g_Ksp[NPART][BB * HH * DK];
__device__ float g_KV[BB * HH * DK * DK];
__device__ float g_Ksum[BB * HH * DK];

// ---------------- tf32 mma.sync GEMM ----------------
// C[m,n] = sum_k A[m,k] * W[n,k] + bias[n], optional phi = elu+1
#define BMg 128
#define BNg 128
#define BKg 32
#define KPAD 36          // 32 + 4 pad floats: conflict-free fragment LDS
#define NSTG 2
#define STAGE_F (128 * KPAD)
#define GEMM_SMEM (2 * NSTG * STAGE_F * 4)   // 73728 bytes -> 2 CTAs/SM

__device__ __forceinline__ uint32_t smem_u32(const void* p) {
    uint32_t a;
    asm("{ .reg .u64 t; cvta.to.shared.u64 t, %1; cvt.u32.u64 %0, t; }" : "=r"(a) : "l"(p));
    return a;
}

__device__ __forceinline__ void cp16(uint32_t dst, const void* src) {
    asm volatile("cp.async.cg.shared.global [%0], [%1], 16;" :: "r"(dst), "l"(src));
}

__device__ __forceinline__ uint32_t to_tf32(float f) {
    uint32_t r;
    asm("cvt.rna.tf32.f32 %0, %1;" : "=r"(r) : "f"(f));
    return r;
}

__device__ __forceinline__ void mma_tf32(float& d0, float& d1, float& d2, float& d3,
                                         uint32_t a0, uint32_t a1, uint32_t a2, uint32_t a3,
                                         uint32_t b0, uint32_t b1) {
    asm volatile(
        "mma.sync.aligned.m16n8k8.row.col.f32.tf32.tf32.f32 "
        "{%0,%1,%2,%3},{%4,%5,%6,%7},{%8,%9},{%0,%1,%2,%3};"
        : "+f"(d0), "+f"(d1), "+f"(d2), "+f"(d3)
        : "r"(a0), "r"(a1), "r"(a2), "r"(a3), "r"(b0), "r"(b1));
}

__global__ void __launch_bounds__(256, 2) gemm_mma(
    const float* __restrict__ A, const float* __restrict__ W,
    const float* __restrict__ bias, float* __restrict__ C, int do_phi)
{
    extern __shared__ float sm[];
    float* As = sm;                       // [NSTG][128][KPAD]
    float* Bs = sm + NSTG * STAGE_F;
    const uint32_t as_u = smem_u32(As), bs_u = smem_u32(Bs);

    const int tid = threadIdx.x;
    const int wid = tid >> 5, lane = tid & 31;
    const int tr = lane >> 2, tc = lane & 3;
    const int m0 = blockIdx.y * BMg, n0 = blockIdx.x * BNg;
    const int wm = (wid & 3) * 32, wn = (wid >> 2) * 64;

    float acc[2][8][4];
#pragma unroll
    for (int i = 0; i < 2; i++)
#pragma unroll
        for (int j = 0; j < 8; j++)
#pragma unroll
            for (int q = 0; q < 4; q++) acc[i][j][q] = 0.f;

    // stage loader: 1024 float4 per operand per stage; 4 per thread
    auto load_stage = [&](int s, int k0) {
#pragma unroll
        for (int i = 0; i < 4; i++) {
            int idx = tid + i * 256;
            int r = idx >> 3, c = idx & 7;
            cp16(as_u + (uint32_t)((s * STAGE_F + r * KPAD + c * 4) * 4),
                 &A[(size_t)(m0 + r) * DDIM + k0 + c * 4]);
            cp16(bs_u + (uint32_t)((s * STAGE_F + r * KPAD + c * 4) * 4),
                 &W[(size_t)(n0 + r) * DDIM + k0 + c * 4]);
        }
        asm volatile("cp.async.commit_group;" ::: "memory");
    };

#pragma unroll
    for (int s = 0; s < NSTG; s++) load_stage(s, s * BKg);

    const int NCHUNK = DDIM / BKg;  // 32
#pragma unroll 1
    for (int ck = 0; ck < NCHUNK; ck++) {
        const int s = ck % NSTG;
        asm volatile("cp.async.wait_group %0;" :: "n"(NSTG - 1) : "memory");
        __syncthreads();

        const float* aw = As + s * STAGE_F + wm * KPAD;
        const float* bw = Bs + s * STAGE_F + wn * KPAD;
#pragma unroll
        for (int ks = 0; ks < 4; ks++) {
            const int kk = ks * 8 + tc;
            uint32_t af[2][4];
#pragma unroll
            for (int mt = 0; mt < 2; mt++) {
                const float* p = aw + (mt * 16 + tr) * KPAD + kk;
                af[mt][0] = to_tf32(p[0]);
                af[mt][1] = to_tf32(p[8 * KPAD]);
                af[mt][2] = to_tf32(p[4]);
                af[mt][3] = to_tf32(p[8 * KPAD + 4]);
            }
            uint32_t bf[8][2];
#pragma unroll
            for (int nt = 0; nt < 8; nt++) {
                const float* p = bw + (nt * 8 + tr) * KPAD + kk;
                bf[nt][0] = to_tf32(p[0]);
                bf[nt][1] = to_tf32(p[4]);
            }
#pragma unroll
            for (int mt = 0; mt < 2; mt++)
#pragma unroll
                for (int nt = 0; nt < 8; nt++)
                    mma_tf32(acc[mt][nt][0], acc[mt][nt][1], acc[mt][nt][2], acc[mt][nt][3],
                             af[mt][0], af[mt][1], af[mt][2], af[mt][3],
                             bf[nt][0], bf[nt][1]);
        }
        __syncthreads();
        if (ck + NSTG < NCHUNK) load_stage(s, (ck + NSTG) * BKg);
    }

    // epilogue: bias (+phi), direct float2 stores (full 32B sectors)
#pragma unroll
    for (int mt = 0; mt < 2; mt++) {
        const int row = m0 + wm + mt * 16 + tr;
#pragma unroll
        for (int nt = 0; nt < 8; nt++) {
            const int col = n0 + wn + nt * 8 + tc * 2;
            const float bv0 = __ldg(&bias[col]), bv1 = __ldg(&bias[col + 1]);
            float v0 = acc[mt][nt][0] + bv0;
            float v1 = acc[mt][nt][1] + bv1;
            float v2 = acc[mt][nt][2] + bv0;
            float v3 = acc[mt][nt][3] + bv1;
            if (do_phi) {
                v0 = (v0 > 0.f) ? (v0 + 1.f) : __expf(v0);
                v1 = (v1 > 0.f) ? (v1 + 1.f) : __expf(v1);
                v2 = (v2 > 0.f) ? (v2 + 1.f) : __expf(v2);
                v3 = (v3 > 0.f) ? (v3 + 1.f) : __expf(v3);
            }
            *(float2*)&C[(size_t)row * DDIM + col]       = make_float2(v0, v1);
            *(float2*)&C[(size_t)(row + 8) * DDIM + col] = make_float2(v2, v3);
        }
    }
}

// ---------------- KV = K^T V per (b,h), split over S into NPART partials ----------------
__global__ __launch_bounds__(256)
void kv_part_kernel()
{
    const int bh = blockIdx.x;            // 0..127
    const int part = blockIdx.y;          // 0..NPART-1
    const int b = bh >> 4, h = bh & 15;
    const int sbeg = part * (SSEQ / NPART), send = sbeg + (SSEQ / NPART);

    const float* Kp = g_K + (size_t)b * SSEQ * DDIM + h * DK;
    const float* Vp = g_V + (size_t)b * SSEQ * DDIM + h * DK;

    __shared__ float Ks[32][DK];
    __shared__ float Vs[32][DK];

    const int tid = threadIdx.x;
    const int r  = tid >> 4;
    const int c4 = tid & 15;
    const int tx = tid & 15, ty = tid >> 4;
    const int d0 = ty * 4, e0 = tx * 4;

    float acc[4][4];
#pragma unroll
    for (int i = 0; i < 4; i++)
#pragma unroll
        for (int j = 0; j < 4; j++) acc[i][j] = 0.f;
    float ks = 0.f;

    for (int s0 = sbeg; s0 < send; s0 += 32) {
        const float* kb = Kp + (size_t)s0 * DDIM;
        const float* vb = Vp + (size_t)s0 * DDIM;
        *(float4*)&Ks[r][c4 * 4]      = *(const float4*)(kb + (size_t)r * DDIM + c4 * 4);
        *(float4*)&Ks[r + 16][c4 * 4] = *(const float4*)(kb + (size_t)(r + 16) * DDIM + c4 * 4);
        *(float4*)&Vs[r][c4 * 4]      = *(const float4*)(vb + (size_t)r * DDIM + c4 * 4);
        *(float4*)&Vs[r + 16][c4 * 4] = *(const float4*)(vb + (size_t)(r + 16) * DDIM + c4 * 4);
        __syncthreads();

#pragma unroll
        for (int s = 0; s < 32; s++) {
            float4 kk = *(const float4*)&Ks[s][d0];
            float4 vv = *(const float4*)&Vs[s][e0];
            float kr[4] = {kk.x, kk.y, kk.z, kk.w};
            float vr[4] = {vv.x, vv.y, vv.z, vv.w};
#pragma unroll
            for (int i = 0; i < 4; i++)
#pragma unroll
                for (int j = 0; j < 4; j++) acc[i][j] += kr[i] * vr[j];
        }
        if (tid < DK) {
#pragma unroll
            for (int s = 0; s < 32; s++) ks += Ks[s][tid];
        }
        __syncthreads();
    }

    float* out = g_KVp[part] + (size_t)bh * DK * DK;
#pragma unroll
    for (int i = 0; i < 4; i++)
#pragma unroll
        for (int j = 0; j < 4; j++) out[(d0 + i) * DK + e0 + j] = acc[i][j];
    if (tid < DK) g_Ksp[part][bh * DK + tid] = ks;
}

__global__ __launch_bounds__(256)
void kv_reduce_kernel()
{
    const int bh = blockIdx.x;
    const int tid = threadIdx.x;
    const size_t base = (size_t)bh * DK * DK;
    for (int i = tid; i < DK * DK; i += 256) {
        float s = 0.f;
#pragma unroll
        for (int p = 0; p < NPART; p++) s += g_KVp[p][base + i];
        g_KV[base + i] = s;
    }
    if (tid < DK) {
        const int o = bh * DK + tid;
        float s = 0.f;
#pragma unroll
        for (int p = 0; p < NPART; p++) s += g_Ksp[p][o];
        g_Ksum[o] = s;
    }
}

// ---------------- out = (Q·KV) / (Q·Ksum + eps) ----------------
__global__ __launch_bounds__(256)
void attn_kernel()
{
    const int bh = blockIdx.y;
    const int b = bh >> 4, h = bh & 15;
    const int s_base = blockIdx.x * 128;

    __shared__ float KVs[DK][DK];
    __shared__ float Ksm[DK];
    __shared__ float Qs[32][DK];

    const int tid = threadIdx.x;

    const float* kvp = g_KV + (size_t)bh * DK * DK;
    for (int i = tid; i < DK * DK / 4; i += 256)
        ((float4*)KVs)[i] = ((const float4*)kvp)[i];
    if (tid < DK) Ksm[tid] = g_Ksum[bh * DK + tid];
    __syncthreads();

    const float* Qp = g_Q + (size_t)b * SSEQ * DDIM + h * DK;
    float* Op       = g_A + (size_t)b * SSEQ * DDIM + h * DK;

    const int r  = tid >> 4;
    const int c4 = tid & 15;
    const int sl = tid >> 3;
    const int g  = tid & 7;
    const int e0 = g * 8;

    for (int c = 0; c < 4; c++) {
        int s0 = s_base + c * 32;
        *(float4*)&Qs[r][c4 * 4]      = *(const float4*)(Qp + (size_t)(s0 + r) * DDIM + c4 * 4);
        *(float4*)&Qs[r + 16][c4 * 4] = *(const float4*)(Qp + (size_t)(s0 + r + 16) * DDIM + c4 * 4);
        __syncthreads();

        float acc[8];
#pragma unroll
        for (int j = 0; j < 8; j++) acc[j] = 0.f;
        float z = 0.f;
#pragma unroll
        for (int d = 0; d < DK; d++) {
            float q = Qs[sl][d];
            z += q * Ksm[d];
#pragma unroll
            for (int j = 0; j < 8; j++) acc[j] += q * KVs[d][e0 + j];
        }
        float invz = 1.f / (z + 1e-6f);
        float* op = Op + (size_t)(s0 + sl) * DDIM + e0;
#pragma unroll
        for (int j = 0; j < 8; j++) op[j] = acc[j] * invz;
        __syncthreads();
    }
}

// ---------------- host ----------------
extern "C" void kernel_launch(void* const* d_in, const int* in_sizes, int n_in,
                              void* d_out, int out_size)
{
    const float* x  = (const float*)d_in[0];
    const float* Wq = (const float*)d_in[1];
    const float* bq = (const float*)d_in[2];
    const float* Wk = (const float*)d_in[3];
    const float* bk = (const float*)d_in[4];
    const float* Wv = (const float*)d_in[5];
    const float* bv = (const float*)d_in[6];
    const float* Wo = (const float*)d_in[7];
    const float* bo = (const float*)d_in[8];

    float *Qb, *Kb, *Vb, *Ab;
    cudaGetSymbolAddress((void**)&Qb, g_Q);
    cudaGetSymbolAddress((void**)&Kb, g_K);
    cudaGetSymbolAddress((void**)&Vb, g_V);
    cudaGetSymbolAddress((void**)&Ab, g_A);

    cudaFuncSetAttribute(gemm_mma, cudaFuncAttributeMaxDynamicSharedMemorySize, GEMM_SMEM);

    dim3 gg(DDIM / BNg, MTOT / BMg);
    gemm_mma<<<gg, 256, GEMM_SMEM>>>(x, Wq, bq, Qb, 1);
    gemm_mma<<<gg, 256, GEMM_SMEM>>>(x, Wk, bk, Kb, 1);
    gemm_mma<<<gg, 256, GEMM_SMEM>>>(x, Wv, bv, Vb, 0);

    kv_part_kernel<<<dim3(BB * HH, NPART), 256>>>();
    kv_reduce_kernel<<<BB * HH, 256>>>();
    attn_kernel<<<dim3(SSEQ / 128, BB * HH), 256>>>();

    gemm_mma<<<gg, 256, GEMM_SMEM>>>(Ab, Wo, bo, (float*)d_out, 0);
}

// round 7
// speedup vs baseline: 5.2701x; 1.7702x over previous
#include <cuda_runtime.h>
#include <cuda_fp16.h>
#include <cstdint>
#include <math.h>

#define MTOT 32768   // B*S
#define DDIM 1024
#define SSEQ 4096
#define BB   8
#define HH   16
#define DK   64
#define NPART 8

// ---------------- scratch (no cudaMalloc allowed) ----------------
__device__ float  g_Q[MTOT * DDIM];
__device__ float  g_K[MTOT * DDIM];
__device__ float  g_V[MTOT * DDIM];
__device__ __half g_Xh[MTOT * DDIM];
__device__ __half g_Ah[MTOT * DDIM];
__device__ __half g_Wh[4][DDIM * DDIM];
__device__ float  g_KVp[NPART][BB * HH * DK * DK];
__device__ float  g_Ksp[NPART][BB * HH * DK];
__device__ float  g_KV[BB * HH * DK * DK];
__device__ float  g_Ksum[BB * HH * DK];

// ---------------- helpers ----------------
__device__ __forceinline__ uint32_t smem_u32(const void* p) {
    uint32_t a;
    asm("{ .reg .u64 t; cvta.to.shared.u64 t, %1; cvt.u32.u64 %0, t; }" : "=r"(a) : "l"(p));
    return a;
}
__device__ __forceinline__ void cp16(uint32_t dst, const void* src) {
    asm volatile("cp.async.cg.shared.global [%0], [%1], 16;" :: "r"(dst), "l"(src));
}
__device__ __forceinline__ void ldm_x4(uint32_t* r, uint32_t addr) {
    asm volatile("ldmatrix.sync.aligned.m8n8.x4.shared.b16 {%0,%1,%2,%3}, [%4];"
                 : "=r"(r[0]), "=r"(r[1]), "=r"(r[2]), "=r"(r[3]) : "r"(addr));
}
__device__ __forceinline__ void mma_f16(float& d0, float& d1, float& d2, float& d3,
                                        uint32_t a0, uint32_t a1, uint32_t a2, uint32_t a3,
                                        uint32_t b0, uint32_t b1) {
    asm volatile(
        "mma.sync.aligned.m16n8k16.row.col.f32.f16.f16.f32 "
        "{%0,%1,%2,%3},{%4,%5,%6,%7},{%8,%9},{%0,%1,%2,%3};"
        : "+f"(d0), "+f"(d1), "+f"(d2), "+f"(d3)
        : "r"(a0), "r"(a1), "r"(a2), "r"(a3), "r"(b0), "r"(b1));
}

// ---------------- fp32 -> fp16 conversion ----------------
__global__ __launch_bounds__(256)
void f2h_kernel(const float* __restrict__ in, __half* __restrict__ out, int n)
{
    int i = (blockIdx.x * 256 + threadIdx.x) * 8;
    if (i < n) {
        float4 v0 = *(const float4*)(in + i);
        float4 v1 = *(const float4*)(in + i + 4);
        __half2 h0 = __floats2half2_rn(v0.x, v0.y);
        __half2 h1 = __floats2half2_rn(v0.z, v0.w);
        __half2 h2 = __floats2half2_rn(v1.x, v1.y);
        __half2 h3 = __floats2half2_rn(v1.z, v1.w);
        uint4 o;
        o.x = *(uint32_t*)&h0; o.y = *(uint32_t*)&h1;
        o.z = *(uint32_t*)&h2; o.w = *(uint32_t*)&h3;
        *(uint4*)(out + i) = o;
    }
}

// ---------------- fp16 mma GEMM: C[m,n] = sum_k A[m,k]*W[n,k] + bias[n] ----------------
#define BMg 128
#define BNg 128
#define BKh 64                 // halfs per chunk -> 128 B per row
#define NSTG 3
#define ASTG (128 * 128)       // bytes per operand tile per stage (128 rows x 128 B)
#define GEMM_SMEM (2 * NSTG * ASTG)   // 98304 bytes

__global__ void __launch_bounds__(256, 2) gemm_h(
    const __half* __restrict__ A, const __half* __restrict__ W,
    const float* __restrict__ bias, float* __restrict__ C, int do_phi)
{
    extern __shared__ char smraw[];
    const uint32_t as_u = smem_u32(smraw);
    const uint32_t bs_u = as_u + NSTG * ASTG;

    const int tid = threadIdx.x;
    const int wid = tid >> 5, lane = tid & 31;
    const int tr = lane >> 2, tc = lane & 3;
    const int m0 = blockIdx.y * BMg, n0 = blockIdx.x * BNg;
    const int wm = (wid & 3) * 32, wn = (wid >> 2) * 64;

    float acc[2][8][4];
#pragma unroll
    for (int i = 0; i < 2; i++)
#pragma unroll
        for (int j = 0; j < 8; j++)
#pragma unroll
            for (int q = 0; q < 4; q++) acc[i][j][q] = 0.f;

    // stage loader: per operand 128 rows x 8 chunks(16B); 4 chunks per thread
    auto load_stage = [&](int s, int k0) {
#pragma unroll
        for (int i = 0; i < 4; i++) {
            int idx = tid + i * 256;
            int r = idx >> 3, c = idx & 7;
            int cs = c ^ (r & 7);
            cp16(as_u + (uint32_t)(s * ASTG + r * 128 + cs * 16),
                 &A[(size_t)(m0 + r) * DDIM + k0 + c * 8]);
            cp16(bs_u + (uint32_t)(s * ASTG + r * 128 + cs * 16),
                 &W[(size_t)(n0 + r) * DDIM + k0 + c * 8]);
        }
        asm volatile("cp.async.commit_group;" ::: "memory");
    };

#pragma unroll
    for (int s = 0; s < NSTG; s++) load_stage(s, s * BKh);

    const int NCHUNK = DDIM / BKh;  // 16
#pragma unroll 1
    for (int ck = 0; ck < NCHUNK; ck++) {
        const int s = ck % NSTG;
        asm volatile("cp.async.wait_group %0;" :: "n"(NSTG - 1) : "memory");
        __syncthreads();

        const uint32_t ab = as_u + s * ASTG;
        const uint32_t bb = bs_u + s * ASTG;
#pragma unroll
        for (int ks = 0; ks < 4; ks++) {
            // A fragments: 2 m-tiles of 16x16
            uint32_t af[2][4];
            {
                const int r = lane & 15, sel = lane >> 4;
#pragma unroll
                for (int mt = 0; mt < 2; mt++) {
                    const int row = wm + mt * 16 + r;
                    const int ch = (ks * 2 + sel) ^ (row & 7);
                    ldm_x4(af[mt], ab + row * 128 + ch * 16);
                }
            }
            // B fragments: 4 pairs of n-tiles (16 n-rows each)
            uint32_t bf[4][4];
            {
                const int g = lane >> 3, rr = lane & 7;
#pragma unroll
                for (int p = 0; p < 4; p++) {
                    const int row = wn + p * 16 + (g >> 1) * 8 + rr;
                    const int ch = (ks * 2 + (g & 1)) ^ (row & 7);
                    ldm_x4(bf[p], bb + row * 128 + ch * 16);
                }
            }
#pragma unroll
            for (int mt = 0; mt < 2; mt++)
#pragma unroll
                for (int p = 0; p < 4; p++) {
                    mma_f16(acc[mt][2*p][0], acc[mt][2*p][1], acc[mt][2*p][2], acc[mt][2*p][3],
                            af[mt][0], af[mt][1], af[mt][2], af[mt][3],
                            bf[p][0], bf[p][1]);
                    mma_f16(acc[mt][2*p+1][0], acc[mt][2*p+1][1], acc[mt][2*p+1][2], acc[mt][2*p+1][3],
                            af[mt][0], af[mt][1], af[mt][2], af[mt][3],
                            bf[p][2], bf[p][3]);
                }
        }
        __syncthreads();
        if (ck + NSTG < NCHUNK) load_stage(s, (ck + NSTG) * BKh);
    }

    // epilogue: bias (+phi), float2 stores
#pragma unroll
    for (int mt = 0; mt < 2; mt++) {
        const int row = m0 + wm + mt * 16 + tr;
#pragma unroll
        for (int nt = 0; nt < 8; nt++) {
            const int col = n0 + wn + nt * 8 + tc * 2;
            const float bv0 = __ldg(&bias[col]), bv1 = __ldg(&bias[col + 1]);
            float v0 = acc[mt][nt][0] + bv0;
            float v1 = acc[mt][nt][1] + bv1;
            float v2 = acc[mt][nt][2] + bv0;
            float v3 = acc[mt][nt][3] + bv1;
            if (do_phi) {
                v0 = (v0 > 0.f) ? (v0 + 1.f) : __expf(v0);
                v1 = (v1 > 0.f) ? (v1 + 1.f) : __expf(v1);
                v2 = (v2 > 0.f) ? (v2 + 1.f) : __expf(v2);
                v3 = (v3 > 0.f) ? (v3 + 1.f) : __expf(v3);
            }
            *(float2*)&C[(size_t)row * DDIM + col]       = make_float2(v0, v1);
            *(float2*)&C[(size_t)(row + 8) * DDIM + col] = make_float2(v2, v3);
        }
    }
}

// ---------------- KV = K^T V per (b,h), split over S into NPART partials ----------------
__global__ __launch_bounds__(256)
void kv_part_kernel()
{
    const int bh = blockIdx.x;
    const int part = blockIdx.y;
    const int b = bh >> 4, h = bh & 15;
    const int sbeg = part * (SSEQ / NPART), send = sbeg + (SSEQ / NPART);

    const float* Kp = g_K + (size_t)b * SSEQ * DDIM + h * DK;
    const float* Vp = g_V + (size_t)b * SSEQ * DDIM + h * DK;

    __shared__ float Ks[32][DK];
    __shared__ float Vs[32][DK];

    const int tid = threadIdx.x;
    const int r  = tid >> 4;
    const int c4 = tid & 15;
    const int tx = tid & 15, ty = tid >> 4;
    const int d0 = ty * 4, e0 = tx * 4;

    float acc[4][4];
#pragma unroll
    for (int i = 0; i < 4; i++)
#pragma unroll
        for (int j = 0; j < 4; j++) acc[i][j] = 0.f;
    float ks = 0.f;

    for (int s0 = sbeg; s0 < send; s0 += 32) {
        const float* kb = Kp + (size_t)s0 * DDIM;
        const float* vb = Vp + (size_t)s0 * DDIM;
        *(float4*)&Ks[r][c4 * 4]      = *(const float4*)(kb + (size_t)r * DDIM + c4 * 4);
        *(float4*)&Ks[r + 16][c4 * 4] = *(const float4*)(kb + (size_t)(r + 16) * DDIM + c4 * 4);
        *(float4*)&Vs[r][c4 * 4]      = *(const float4*)(vb + (size_t)r * DDIM + c4 * 4);
        *(float4*)&Vs[r + 16][c4 * 4] = *(const float4*)(vb + (size_t)(r + 16) * DDIM + c4 * 4);
        __syncthreads();

#pragma unroll
        for (int s = 0; s < 32; s++) {
            float4 kk = *(const float4*)&Ks[s][d0];
            float4 vv = *(const float4*)&Vs[s][e0];
            float kr[4] = {kk.x, kk.y, kk.z, kk.w};
            float vr[4] = {vv.x, vv.y, vv.z, vv.w};
#pragma unroll
            for (int i = 0; i < 4; i++)
#pragma unroll
                for (int j = 0; j < 4; j++) acc[i][j] += kr[i] * vr[j];
        }
        if (tid < DK) {
#pragma unroll
            for (int s = 0; s < 32; s++) ks += Ks[s][tid];
        }
        __syncthreads();
    }

    float* out = g_KVp[part] + (size_t)bh * DK * DK;
#pragma unroll
    for (int i = 0; i < 4; i++)
#pragma unroll
        for (int j = 0; j < 4; j++) out[(d0 + i) * DK + e0 + j] = acc[i][j];
    if (tid < DK) g_Ksp[part][bh * DK + tid] = ks;
}

__global__ __launch_bounds__(256)
void kv_reduce_kernel()
{
    const int bh = blockIdx.x;
    const int tid = threadIdx.x;
    const size_t base = (size_t)bh * DK * DK;
    for (int i = tid; i < DK * DK; i += 256) {
        float s = 0.f;
#pragma unroll
        for (int p = 0; p < NPART; p++) s += g_KVp[p][base + i];
        g_KV[base + i] = s;
    }
    if (tid < DK) {
        const int o = bh * DK + tid;
        float s = 0.f;
#pragma unroll
        for (int p = 0; p < NPART; p++) s += g_Ksp[p][o];
        g_Ksum[o] = s;
    }
}

// ---------------- out = (Q·KV)/(Q·Ksum+eps), written as fp16 for final GEMM ----------------
__global__ __launch_bounds__(256)
void attn_kernel()
{
    const int bh = blockIdx.y;
    const int b = bh >> 4, h = bh & 15;
    const int s_base = blockIdx.x * 128;

    __shared__ float KVs[DK][DK];
    __shared__ float Ksm[DK];
    __shared__ float Qs[32][DK];

    const int tid = threadIdx.x;

    const float* kvp = g_KV + (size_t)bh * DK * DK;
    for (int i = tid; i < DK * DK / 4; i += 256)
        ((float4*)KVs)[i] = ((const float4*)kvp)[i];
    if (tid < DK) Ksm[tid] = g_Ksum[bh * DK + tid];
    __syncthreads();

    const float* Qp = g_Q + (size_t)b * SSEQ * DDIM + h * DK;
    __half* Op      = g_Ah + (size_t)b * SSEQ * DDIM + h * DK;

    const int r  = tid >> 4;
    const int c4 = tid & 15;
    const int sl = tid >> 3;
    const int g  = tid & 7;
    const int e0 = g * 8;

    for (int c = 0; c < 4; c++) {
        int s0 = s_base + c * 32;
        *(float4*)&Qs[r][c4 * 4]      = *(const float4*)(Qp + (size_t)(s0 + r) * DDIM + c4 * 4);
        *(float4*)&Qs[r + 16][c4 * 4] = *(const float4*)(Qp + (size_t)(s0 + r + 16) * DDIM + c4 * 4);
        __syncthreads();

        float acc[8];
#pragma unroll
        for (int j = 0; j < 8; j++) acc[j] = 0.f;
        float z = 0.f;
#pragma unroll
        for (int d = 0; d < DK; d++) {
            float q = Qs[sl][d];
            z += q * Ksm[d];
#pragma unroll
            for (int j = 0; j < 8; j++) acc[j] += q * KVs[d][e0 + j];
        }
        float invz = 1.f / (z + 1e-6f);
        __half2 h0 = __floats2half2_rn(acc[0] * invz, acc[1] * invz);
        __half2 h1 = __floats2half2_rn(acc[2] * invz, acc[3] * invz);
        __half2 h2 = __floats2half2_rn(acc[4] * invz, acc[5] * invz);
        __half2 h3 = __floats2half2_rn(acc[6] * invz, acc[7] * invz);
        uint4 o;
        o.x = *(uint32_t*)&h0; o.y = *(uint32_t*)&h1;
        o.z = *(uint32_t*)&h2; o.w = *(uint32_t*)&h3;
        *(uint4*)(Op + (size_t)(s0 + sl) * DDIM + e0) = o;
        __syncthreads();
    }
}

// ---------------- host ----------------
extern "C" void kernel_launch(void* const* d_in, const int* in_sizes, int n_in,
                              void* d_out, int out_size)
{
    const float* x  = (const float*)d_in[0];
    const float* Wq = (const float*)d_in[1];
    const float* bq = (const float*)d_in[2];
    const float* Wk = (const float*)d_in[3];
    const float* bk = (const float*)d_in[4];
    const float* Wv = (const float*)d_in[5];
    const float* bv = (const float*)d_in[6];
    const float* Wo = (const float*)d_in[7];
    const float* bo = (const float*)d_in[8];

    float *Qb, *Kb, *Vb;
    __half *Xh, *Ah, *Wh;
    cudaGetSymbolAddress((void**)&Qb, g_Q);
    cudaGetSymbolAddress((void**)&Kb, g_K);
    cudaGetSymbolAddress((void**)&Vb, g_V);
    cudaGetSymbolAddress((void**)&Xh, g_Xh);
    cudaGetSymbolAddress((void**)&Ah, g_Ah);
    cudaGetSymbolAddress((void**)&Wh, g_Wh);

    __half* Whq = Wh;
    __half* Whk = Wh + (size_t)DDIM * DDIM;
    __half* Whv = Wh + 2 * (size_t)DDIM * DDIM;
    __half* Who = Wh + 3 * (size_t)DDIM * DDIM;

    cudaFuncSetAttribute(gemm_h, cudaFuncAttributeMaxDynamicSharedMemorySize, GEMM_SMEM);

    const int NX = MTOT * DDIM;
    const int NW = DDIM * DDIM;
    f2h_kernel<<<NX / 8 / 256, 256>>>(x, Xh, NX);
    f2h_kernel<<<NW / 8 / 256, 256>>>(Wq, Whq, NW);
    f2h_kernel<<<NW / 8 / 256, 256>>>(Wk, Whk, NW);
    f2h_kernel<<<NW / 8 / 256, 256>>>(Wv, Whv, NW);
    f2h_kernel<<<NW / 8 / 256, 256>>>(Wo, Who, NW);

    dim3 gg(DDIM / BNg, MTOT / BMg);
    gemm_h<<<gg, 256, GEMM_SMEM>>>(Xh, Whq, bq, Qb, 1);
    gemm_h<<<gg, 256, GEMM_SMEM>>>(Xh, Whk, bk, Kb, 1);
    gemm_h<<<gg, 256, GEMM_SMEM>>>(Xh, Whv, bv, Vb, 0);

    kv_part_kernel<<<dim3(BB * HH, NPART), 256>>>();
    kv_reduce_kernel<<<BB * HH, 256>>>();
    attn_kernel<<<dim3(SSEQ / 128, BB * HH), 256>>>();

    gemm_h<<<gg, 256, GEMM_SMEM>>>(Ah, Who, bo, (float*)d_out, 0);
}

// round 11
// speedup vs baseline: 7.8052x; 1.4810x over previous
#include <cuda_runtime.h>
#include <cuda_fp16.h>
#include <cstdint>
#include <math.h>

#define MTOT 32768   // B*S
#define DDIM 1024
#define SSEQ 4096
#define BB   8
#define HH   16
#define DK   64
#define NPART 8

// ---------------- scratch (no cudaMalloc allowed) ----------------
__device__ __half g_Xh[MTOT * DDIM];
__device__ __half g_Qh[MTOT * DDIM];
__device__ float  g_K[MTOT * DDIM];
__device__ float  g_V[MTOT * DDIM];
__device__ __half g_Ah[MTOT * DDIM];
__device__ __half g_Wh[4][DDIM * DDIM];
__device__ float  g_KVp[NPART][BB * HH * DK * DK];
__device__ float  g_Ksp[NPART][BB * HH * DK];
__device__ __half g_KVh[BB * HH * DK * DK];   // transposed: [bh][e][d]
__device__ float  g_Ksum[BB * HH * DK];

// ---------------- helpers ----------------
__device__ __forceinline__ uint32_t smem_u32(const void* p) {
    uint32_t a;
    asm("{ .reg .u64 t; cvta.to.shared.u64 t, %1; cvt.u32.u64 %0, t; }" : "=r"(a) : "l"(p));
    return a;
}
__device__ __forceinline__ void cp16(uint32_t dst, const void* src) {
    asm volatile("cp.async.cg.shared.global [%0], [%1], 16;" :: "r"(dst), "l"(src));
}
__device__ __forceinline__ void ldm_x4(uint32_t* r, uint32_t addr) {
    asm volatile("ldmatrix.sync.aligned.m8n8.x4.shared.b16 {%0,%1,%2,%3}, [%4];"
                 : "=r"(r[0]), "=r"(r[1]), "=r"(r[2]), "=r"(r[3]) : "r"(addr));
}
__device__ __forceinline__ void mma_f16(float& d0, float& d1, float& d2, float& d3,
                                        uint32_t a0, uint32_t a1, uint32_t a2, uint32_t a3,
                                        uint32_t b0, uint32_t b1) {
    asm volatile(
        "mma.sync.aligned.m16n8k16.row.col.f32.f16.f16.f32 "
        "{%0,%1,%2,%3},{%4,%5,%6,%7},{%8,%9},{%0,%1,%2,%3};"
        : "+f"(d0), "+f"(d1), "+f"(d2), "+f"(d3)
        : "r"(a0), "r"(a1), "r"(a2), "r"(a3), "r"(b0), "r"(b1));
}

// ---------------- fp32 -> fp16 ----------------
__global__ __launch_bounds__(256)
void f2h_kernel(const float* __restrict__ in, __half* __restrict__ out, int n)
{
    int i = (blockIdx.x * 256 + threadIdx.x) * 8;
    if (i < n) {
        float4 v0 = *(const float4*)(in + i);
        float4 v1 = *(const float4*)(in + i + 4);
        __half2 h0 = __floats2half2_rn(v0.x, v0.y);
        __half2 h1 = __floats2half2_rn(v0.z, v0.w);
        __half2 h2 = __floats2half2_rn(v1.x, v1.y);
        __half2 h3 = __floats2half2_rn(v1.z, v1.w);
        uint4 o;
        o.x = *(uint32_t*)&h0; o.y = *(uint32_t*)&h1;
        o.z = *(uint32_t*)&h2; o.w = *(uint32_t*)&h3;
        *(uint4*)(out + i) = o;
    }
}

// ---------------- fp16 mma GEMM: C = A*W^T + bias; fp32 or fp16 out ----------------
#define BMg 128
#define BNg 128
#define BKh 64
#define NSTG 3
#define ASTG (128 * 128)
#define GEMM_SMEM (2 * NSTG * ASTG)   // 98304

__global__ void __launch_bounds__(256, 2) gemm_h(
    const __half* __restrict__ A, const __half* __restrict__ W,
    const float* __restrict__ bias, float* __restrict__ Cf,
    __half* __restrict__ Ch, int do_phi)
{
    extern __shared__ char smraw[];
    const uint32_t as_u = smem_u32(smraw);
    const uint32_t bs_u = as_u + NSTG * ASTG;

    const int tid = threadIdx.x;
    const int wid = tid >> 5, lane = tid & 31;
    const int tr = lane >> 2, tc = lane & 3;
    const int m0 = blockIdx.y * BMg, n0 = blockIdx.x * BNg;
    const int wm = (wid & 3) * 32, wn = (wid >> 2) * 64;

    float acc[2][8][4];
#pragma unroll
    for (int i = 0; i < 2; i++)
#pragma unroll
        for (int j = 0; j < 8; j++)
#pragma unroll
            for (int q = 0; q < 4; q++) acc[i][j][q] = 0.f;

    auto load_stage = [&](int s, int k0) {
#pragma unroll
        for (int i = 0; i < 4; i++) {
            int idx = tid + i * 256;
            int r = idx >> 3, c = idx & 7;
            int cs = c ^ (r & 7);
            cp16(as_u + (uint32_t)(s * ASTG + r * 128 + cs * 16),
                 &A[(size_t)(m0 + r) * DDIM + k0 + c * 8]);
            cp16(bs_u + (uint32_t)(s * ASTG + r * 128 + cs * 16),
                 &W[(size_t)(n0 + r) * DDIM + k0 + c * 8]);
        }
        asm volatile("cp.async.commit_group;" ::: "memory");
    };

#pragma unroll
    for (int s = 0; s < NSTG; s++) load_stage(s, s * BKh);

    const int NCHUNK = DDIM / BKh;  // 16
#pragma unroll 1
    for (int ck = 0; ck < NCHUNK; ck++) {
        const int s = ck % NSTG;
        asm volatile("cp.async.wait_group %0;" :: "n"(NSTG - 1) : "memory");
        __syncthreads();

        const uint32_t ab = as_u + s * ASTG;
        const uint32_t bb = bs_u + s * ASTG;
#pragma unroll
        for (int ks = 0; ks < 4; ks++) {
            uint32_t af[2][4];
            {
                const int r = lane & 15, sel = lane >> 4;
#pragma unroll
                for (int mt = 0; mt < 2; mt++) {
                    const int row = wm + mt * 16 + r;
                    const int ch = (ks * 2 + sel) ^ (row & 7);
                    ldm_x4(af[mt], ab + row * 128 + ch * 16);
                }
            }
            uint32_t bf[4][4];
            {
                const int g = lane >> 3, rr = lane & 7;
#pragma unroll
                for (int p = 0; p < 4; p++) {
                    const int row = wn + p * 16 + (g >> 1) * 8 + rr;
                    const int ch = (ks * 2 + (g & 1)) ^ (row & 7);
                    ldm_x4(bf[p], bb + row * 128 + ch * 16);
                }
            }
#pragma unroll
            for (int mt = 0; mt < 2; mt++)
#pragma unroll
                for (int p = 0; p < 4; p++) {
                    mma_f16(acc[mt][2*p][0], acc[mt][2*p][1], acc[mt][2*p][2], acc[mt][2*p][3],
                            af[mt][0], af[mt][1], af[mt][2], af[mt][3],
                            bf[p][0], bf[p][1]);
                    mma_f16(acc[mt][2*p+1][0], acc[mt][2*p+1][1], acc[mt][2*p+1][2], acc[mt][2*p+1][3],
                            af[mt][0], af[mt][1], af[mt][2], af[mt][3],
                            bf[p][2], bf[p][3]);
                }
        }
        __syncthreads();
        if (ck + NSTG < NCHUNK) load_stage(s, (ck + NSTG) * BKh);
    }

#pragma unroll
    for (int mt = 0; mt < 2; mt++) {
        const int row = m0 + wm + mt * 16 + tr;
#pragma unroll
        for (int nt = 0; nt < 8; nt++) {
            const int col = n0 + wn + nt * 8 + tc * 2;
            const float bv0 = __ldg(&bias[col]), bv1 = __ldg(&bias[col + 1]);
            float v0 = acc[mt][nt][0] + bv0;
            float v1 = acc[mt][nt][1] + bv1;
            float v2 = acc[mt][nt][2] + bv0;
            float v3 = acc[mt][nt][3] + bv1;
            if (do_phi) {
                v0 = (v0 > 0.f) ? (v0 + 1.f) : __expf(v0);
                v1 = (v1 > 0.f) ? (v1 + 1.f) : __expf(v1);
                v2 = (v2 > 0.f) ? (v2 + 1.f) : __expf(v2);
                v3 = (v3 > 0.f) ? (v3 + 1.f) : __expf(v3);
            }
            if (Ch) {
                __half2 a = __floats2half2_rn(v0, v1);
                __half2 b = __floats2half2_rn(v2, v3);
                *(__half2*)&Ch[(size_t)row * DDIM + col]       = a;
                *(__half2*)&Ch[(size_t)(row + 8) * DDIM + col] = b;
            } else {
                *(float2*)&Cf[(size_t)row * DDIM + col]       = make_float2(v0, v1);
                *(float2*)&Cf[(size_t)(row + 8) * DDIM + col] = make_float2(v2, v3);
            }
        }
    }
}

// ---------------- KV = K^T V per (b,h), SIMT fp32 (proven) ----------------
__global__ __launch_bounds__(256)
void kv_part_kernel()
{
    const int bh = blockIdx.x;
    const int part = blockIdx.y;
    const int b = bh >> 4, h = bh & 15;
    const int sbeg = part * (SSEQ / NPART), send = sbeg + (SSEQ / NPART);

    const float* Kp = g_K + (size_t)b * SSEQ * DDIM + h * DK;
    const float* Vp = g_V + (size_t)b * SSEQ * DDIM + h * DK;

    __shared__ float Ks[32][DK];
    __shared__ float Vs[32][DK];

    const int tid = threadIdx.x;
    const int r  = tid >> 4;
    const int c4 = tid & 15;
    const int tx = tid & 15, ty = tid >> 4;
    const int d0 = ty * 4, e0 = tx * 4;

    float acc[4][4];
#pragma unroll
    for (int i = 0; i < 4; i++)
#pragma unroll
        for (int j = 0; j < 4; j++) acc[i][j] = 0.f;
    float ks = 0.f;

    for (int s0 = sbeg; s0 < send; s0 += 32) {
        const float* kb = Kp + (size_t)s0 * DDIM;
        const float* vb = Vp + (size_t)s0 * DDIM;
        *(float4*)&Ks[r][c4 * 4]      = *(const float4*)(kb + (size_t)r * DDIM + c4 * 4);
        *(float4*)&Ks[r + 16][c4 * 4] = *(const float4*)(kb + (size_t)(r + 16) * DDIM + c4 * 4);
        *(float4*)&Vs[r][c4 * 4]      = *(const float4*)(vb + (size_t)r * DDIM + c4 * 4);
        *(float4*)&Vs[r + 16][c4 * 4] = *(const float4*)(vb + (size_t)(r + 16) * DDIM + c4 * 4);
        __syncthreads();

#pragma unroll
        for (int s = 0; s < 32; s++) {
            float4 kk = *(const float4*)&Ks[s][d0];
            float4 vv = *(const float4*)&Vs[s][e0];
            float kr[4] = {kk.x, kk.y, kk.z, kk.w};
            float vr[4] = {vv.x, vv.y, vv.z, vv.w};
#pragma unroll
            for (int i = 0; i < 4; i++)
#pragma unroll
                for (int j = 0; j < 4; j++) acc[i][j] += kr[i] * vr[j];
        }
        if (tid < DK) {
#pragma unroll
            for (int s = 0; s < 32; s++) ks += Ks[s][tid];
        }
        __syncthreads();
    }

    float* out = g_KVp[part] + (size_t)bh * DK * DK;
#pragma unroll
    for (int i = 0; i < 4; i++)
#pragma unroll
        for (int j = 0; j < 4; j++) out[(d0 + i) * DK + e0 + j] = acc[i][j];
    if (tid < DK) g_Ksp[part][bh * DK + tid] = ks;
}

// ---------------- reduce partials -> KVh (transposed [e][d], fp16) + Ksum fp32 ----------------
__global__ __launch_bounds__(256)
void kv_reduce_kernel()
{
    const int bh = blockIdx.x;
    const int tid = threadIdx.x;
    const size_t base = (size_t)bh * DK * DK;
    for (int i = tid; i < DK * DK; i += 256) {
        float s = 0.f;
#pragma unroll
        for (int p = 0; p < NPART; p++) s += g_KVp[p][base + i];
        const int d = i >> 6, e = i & 63;
        g_KVh[base + (size_t)e * DK + d] = __float2half_rn(s);
    }
    if (tid < DK) {
        const int o = bh * DK + tid;
        float s = 0.f;
#pragma unroll
        for (int p = 0; p < NPART; p++) s += g_Ksp[p][o];
        g_Ksum[o] = s;
    }
}

// ---------------- attn: out = (Q·KV)/(Q·Ksum+eps) via fp16 mma ----------------
__global__ __launch_bounds__(256)
void attn_mma_kernel()
{
    __shared__ char qsm[128 * 128];    // Q tile fp16: 128 rows x 128B (swizzled)
    __shared__ char kvsm[64 * 128];    // KVT fp16: 64 e-rows x 128B (swizzled)
    __shared__ float Ksm[DK];
    __shared__ float zs[128];
    const uint32_t q_u = smem_u32(qsm);
    const uint32_t kv_u = smem_u32(kvsm);

    const int bh = blockIdx.y;
    const int b = bh >> 4, h = bh & 15;
    const int s_base = blockIdx.x * 128;

    const __half* Qp  = g_Qh + (size_t)b * SSEQ * DDIM + h * DK;
    const __half* KVp = g_KVh + (size_t)bh * DK * DK;
    __half* Op        = g_Ah + (size_t)b * SSEQ * DDIM + h * DK;

    const int tid = threadIdx.x;
    const int wid = tid >> 5, lane = tid & 31;

#pragma unroll
    for (int i = 0; i < 4; i++) {
        int idx = tid + i * 256;
        int r = idx >> 3, c = idx & 7;
        int cs = c ^ (r & 7);
        cp16(q_u + (uint32_t)(r * 128 + cs * 16),
             &Qp[(size_t)(s_base + r) * DDIM + c * 8]);
    }
#pragma unroll
    for (int i = 0; i < 2; i++) {
        int idx = tid + i * 256;
        int r = idx >> 3, c = idx & 7;
        int cs = c ^ (r & 7);
        cp16(kv_u + (uint32_t)(r * 128 + cs * 16), &KVp[(size_t)r * DK + c * 8]);
    }
    if (tid < DK) Ksm[tid] = g_Ksum[bh * DK + tid];
    asm volatile("cp.async.commit_group;" ::: "memory");
    asm volatile("cp.async.wait_group 0;" ::: "memory");
    __syncthreads();

    // z per row (threads 0-127)
    if (tid < 128) {
        const int r = tid;
        float z = 0.f;
#pragma unroll
        for (int d = 0; d < DK; d++) {
            __half hv = *(const __half*)(qsm + r * 128 + (((d >> 3) ^ (r & 7)) * 16) + (d & 7) * 2);
            z += __half2float(hv) * Ksm[d];
        }
        zs[r] = 1.f / (z + 1e-6f);
    }

    const int wm = wid * 16;
    float acc[8][4];
#pragma unroll
    for (int j = 0; j < 8; j++)
#pragma unroll
        for (int q = 0; q < 4; q++) acc[j][q] = 0.f;

#pragma unroll
    for (int ks = 0; ks < 4; ks++) {
        uint32_t af[4];
        {
            const int r = lane & 15, sel = lane >> 4;
            const int row = wm + r;
            const int ch = (ks * 2 + sel) ^ (row & 7);
            ldm_x4(af, q_u + row * 128 + ch * 16);
        }
        uint32_t bf[4][4];
        {
            const int g = lane >> 3, rr = lane & 7;
#pragma unroll
            for (int p = 0; p < 4; p++) {
                const int row = p * 16 + (g >> 1) * 8 + rr;
                const int ch = (ks * 2 + (g & 1)) ^ (row & 7);
                ldm_x4(bf[p], kv_u + row * 128 + ch * 16);
            }
        }
#pragma unroll
        for (int p = 0; p < 4; p++) {
            mma_f16(acc[2*p][0], acc[2*p][1], acc[2*p][2], acc[2*p][3],
                    af[0], af[1], af[2], af[3], bf[p][0], bf[p][1]);
            mma_f16(acc[2*p+1][0], acc[2*p+1][1], acc[2*p+1][2], acc[2*p+1][3],
                    af[0], af[1], af[2], af[3], bf[p][2], bf[p][3]);
        }
    }
    __syncthreads();

    const int tr = lane >> 2, tc = lane & 3;
    const float iz0 = zs[wm + tr], iz1 = zs[wm + tr + 8];
#pragma unroll
    for (int nt = 0; nt < 8; nt++) {
        const int e = nt * 8 + tc * 2;
        __half2 o0 = __floats2half2_rn(acc[nt][0] * iz0, acc[nt][1] * iz0);
        __half2 o1 = __floats2half2_rn(acc[nt][2] * iz1, acc[nt][3] * iz1);
        *(__half2*)&Op[(size_t)(s_base + wm + tr) * DDIM + e]     = o0;
        *(__half2*)&Op[(size_t)(s_base + wm + tr + 8) * DDIM + e] = o1;
    }
}

// ---------------- host ----------------
extern "C" void kernel_launch(void* const* d_in, const int* in_sizes, int n_in,
                              void* d_out, int out_size)
{
    const float* x  = (const float*)d_in[0];
    const float* Wq = (const float*)d_in[1];
    const float* bq = (const float*)d_in[2];
    const float* Wk = (const float*)d_in[3];
    const float* bk = (const float*)d_in[4];
    const float* Wv = (const float*)d_in[5];
    const float* bv = (const float*)d_in[6];
    const float* Wo = (const float*)d_in[7];
    const float* bo = (const float*)d_in[8];

    __half *Xh, *Qh, *Ah, *Wh;
    float *Kb, *Vb;
    cudaGetSymbolAddress((void**)&Xh, g_Xh);
    cudaGetSymbolAddress((void**)&Qh, g_Qh);
    cudaGetSymbolAddress((void**)&Kb, g_K);
    cudaGetSymbolAddress((void**)&Vb, g_V);
    cudaGetSymbolAddress((void**)&Ah, g_Ah);
    cudaGetSymbolAddress((void**)&Wh, g_Wh);

    __half* Whq = Wh;
    __half* Whk = Wh + (size_t)DDIM * DDIM;
    __half* Whv = Wh + 2 * (size_t)DDIM * DDIM;
    __half* Who = Wh + 3 * (size_t)DDIM * DDIM;

    cudaFuncSetAttribute(gemm_h, cudaFuncAttributeMaxDynamicSharedMemorySize, GEMM_SMEM);

    const int NX = MTOT * DDIM;
    const int NW = DDIM * DDIM;
    f2h_kernel<<<NX / 8 / 256, 256>>>(x, Xh, NX);
    f2h_kernel<<<NW / 8 / 256, 256>>>(Wq, Whq, NW);
    f2h_kernel<<<NW / 8 / 256, 256>>>(Wk, Whk, NW);
    f2h_kernel<<<NW / 8 / 256, 256>>>(Wv, Whv, NW);
    f2h_kernel<<<NW / 8 / 256, 256>>>(Wo, Who, NW);

    dim3 gg(DDIM / BNg, MTOT / BMg);
    gemm_h<<<gg, 256, GEMM_SMEM>>>(Xh, Whq, bq, nullptr, Qh, 1);
    gemm_h<<<gg, 256, GEMM_SMEM>>>(Xh, Whk, bk, Kb, nullptr, 1);
    gemm_h<<<gg, 256, GEMM_SMEM>>>(Xh, Whv, bv, Vb, nullptr, 0);

    kv_part_kernel<<<dim3(BB * HH, NPART), 256>>>();
    kv_reduce_kernel<<<BB * HH, 256>>>();
    attn_mma_kernel<<<dim3(SSEQ / 128, BB * HH), 256>>>();

    gemm_h<<<gg, 256, GEMM_SMEM>>>(Ah, Who, bo, (float*)d_out, nullptr, 0);
}

// round 12
// speedup vs baseline: 8.0409x; 1.0302x over previous
#include <cuda_runtime.h>
#include <cuda_fp16.h>
#include <cstdint>
#include <math.h>

#define MTOT 32768   // B*S
#define DDIM 1024
#define SSEQ 4096
#define BB   8
#define HH   16
#define DK   64
#define NPART 16

// ---------------- scratch (no cudaMalloc allowed) ----------------
__device__ __half g_Xh[MTOT * DDIM];
__device__ __half g_Qh[MTOT * DDIM];
__device__ __half g_Kh[MTOT * DDIM];
__device__ __half g_Vh[MTOT * DDIM];
__device__ __half g_Ah[MTOT * DDIM];
__device__ __half g_Wh[4][DDIM * DDIM];
__device__ float  g_KVp[NPART][BB * HH * DK * DK];
__device__ float  g_Ksp[NPART][BB * HH * DK];
__device__ __half g_KVh[BB * HH * DK * DK];   // transposed: [bh][e][d]
__device__ float  g_Ksum[BB * HH * DK];

// ---------------- helpers ----------------
__device__ __forceinline__ uint32_t smem_u32(const void* p) {
    uint32_t a;
    asm("{ .reg .u64 t; cvta.to.shared.u64 t, %1; cvt.u32.u64 %0, t; }" : "=r"(a) : "l"(p));
    return a;
}
__device__ __forceinline__ void cp16(uint32_t dst, const void* src) {
    asm volatile("cp.async.cg.shared.global [%0], [%1], 16;" :: "r"(dst), "l"(src));
}
__device__ __forceinline__ void ldm_x4(uint32_t* r, uint32_t addr) {
    asm volatile("ldmatrix.sync.aligned.m8n8.x4.shared.b16 {%0,%1,%2,%3}, [%4];"
                 : "=r"(r[0]), "=r"(r[1]), "=r"(r[2]), "=r"(r[3]) : "r"(addr));
}
__device__ __forceinline__ void mma_f16(float& d0, float& d1, float& d2, float& d3,
                                        uint32_t a0, uint32_t a1, uint32_t a2, uint32_t a3,
                                        uint32_t b0, uint32_t b1) {
    asm volatile(
        "mma.sync.aligned.m16n8k16.row.col.f32.f16.f16.f32 "
        "{%0,%1,%2,%3},{%4,%5,%6,%7},{%8,%9},{%0,%1,%2,%3};"
        : "+f"(d0), "+f"(d1), "+f"(d2), "+f"(d3)
        : "r"(a0), "r"(a1), "r"(a2), "r"(a3), "r"(b0), "r"(b1));
}

// ---------------- fp32 -> fp16 ----------------
__global__ __launch_bounds__(256)
void f2h_kernel(const float* __restrict__ in, __half* __restrict__ out, int n)
{
    int i = (blockIdx.x * 256 + threadIdx.x) * 8;
    if (i < n) {
        float4 v0 = *(const float4*)(in + i);
        float4 v1 = *(const float4*)(in + i + 4);
        __half2 h0 = __floats2half2_rn(v0.x, v0.y);
        __half2 h1 = __floats2half2_rn(v0.z, v0.w);
        __half2 h2 = __floats2half2_rn(v1.x, v1.y);
        __half2 h3 = __floats2half2_rn(v1.z, v1.w);
        uint4 o;
        o.x = *(uint32_t*)&h0; o.y = *(uint32_t*)&h1;
        o.z = *(uint32_t*)&h2; o.w = *(uint32_t*)&h3;
        *(uint4*)(out + i) = o;
    }
}

// ---------------- fp16 mma GEMM: C = A*W^T + bias; fp32 or fp16 out ----------------
#define BMg 128
#define BNg 128
#define BKh 64
#define NSTG 3
#define ASTG (128 * 128)
#define GEMM_SMEM (2 * NSTG * ASTG)   // 98304

__global__ void __launch_bounds__(256, 2) gemm_h(
    const __half* __restrict__ A, const __half* __restrict__ W,
    const float* __restrict__ bias, float* __restrict__ Cf,
    __half* __restrict__ Ch, int do_phi)
{
    extern __shared__ char smraw[];
    const uint32_t as_u = smem_u32(smraw);
    const uint32_t bs_u = as_u + NSTG * ASTG;

    const int tid = threadIdx.x;
    const int wid = tid >> 5, lane = tid & 31;
    const int tr = lane >> 2, tc = lane & 3;
    const int m0 = blockIdx.y * BMg, n0 = blockIdx.x * BNg;
    const int wm = (wid & 3) * 32, wn = (wid >> 2) * 64;

    float acc[2][8][4];
#pragma unroll
    for (int i = 0; i < 2; i++)
#pragma unroll
        for (int j = 0; j < 8; j++)
#pragma unroll
            for (int q = 0; q < 4; q++) acc[i][j][q] = 0.f;

    auto load_stage = [&](int s, int k0) {
#pragma unroll
        for (int i = 0; i < 4; i++) {
            int idx = tid + i * 256;
            int r = idx >> 3, c = idx & 7;
            int cs = c ^ (r & 7);
            cp16(as_u + (uint32_t)(s * ASTG + r * 128 + cs * 16),
                 &A[(size_t)(m0 + r) * DDIM + k0 + c * 8]);
            cp16(bs_u + (uint32_t)(s * ASTG + r * 128 + cs * 16),
                 &W[(size_t)(n0 + r) * DDIM + k0 + c * 8]);
        }
        asm volatile("cp.async.commit_group;" ::: "memory");
    };

#pragma unroll
    for (int s = 0; s < NSTG; s++) load_stage(s, s * BKh);

    const int NCHUNK = DDIM / BKh;  // 16
#pragma unroll 1
    for (int ck = 0; ck < NCHUNK; ck++) {
        const int s = ck % NSTG;
        asm volatile("cp.async.wait_group %0;" :: "n"(NSTG - 1) : "memory");
        __syncthreads();

        const uint32_t ab = as_u + s * ASTG;
        const uint32_t bb = bs_u + s * ASTG;
#pragma unroll
        for (int ks = 0; ks < 4; ks++) {
            uint32_t af[2][4];
            {
                const int r = lane & 15, sel = lane >> 4;
#pragma unroll
                for (int mt = 0; mt < 2; mt++) {
                    const int row = wm + mt * 16 + r;
                    const int ch = (ks * 2 + sel) ^ (row & 7);
                    ldm_x4(af[mt], ab + row * 128 + ch * 16);
                }
            }
            uint32_t bf[4][4];
            {
                const int g = lane >> 3, rr = lane & 7;
#pragma unroll
                for (int p = 0; p < 4; p++) {
                    const int row = wn + p * 16 + (g >> 1) * 8 + rr;
                    const int ch = (ks * 2 + (g & 1)) ^ (row & 7);
                    ldm_x4(bf[p], bb + row * 128 + ch * 16);
                }
            }
#pragma unroll
            for (int mt = 0; mt < 2; mt++)
#pragma unroll
                for (int p = 0; p < 4; p++) {
                    mma_f16(acc[mt][2*p][0], acc[mt][2*p][1], acc[mt][2*p][2], acc[mt][2*p][3],
                            af[mt][0], af[mt][1], af[mt][2], af[mt][3],
                            bf[p][0], bf[p][1]);
                    mma_f16(acc[mt][2*p+1][0], acc[mt][2*p+1][1], acc[mt][2*p+1][2], acc[mt][2*p+1][3],
                            af[mt][0], af[mt][1], af[mt][2], af[mt][3],
                            bf[p][2], bf[p][3]);
                }
        }
        __syncthreads();
        if (ck + NSTG < NCHUNK) load_stage(s, (ck + NSTG) * BKh);
    }

#pragma unroll
    for (int mt = 0; mt < 2; mt++) {
        const int row = m0 + wm + mt * 16 + tr;
#pragma unroll
        for (int nt = 0; nt < 8; nt++) {
            const int col = n0 + wn + nt * 8 + tc * 2;
            const float bv0 = __ldg(&bias[col]), bv1 = __ldg(&bias[col + 1]);
            float v0 = acc[mt][nt][0] + bv0;
            float v1 = acc[mt][nt][1] + bv1;
            float v2 = acc[mt][nt][2] + bv0;
            float v3 = acc[mt][nt][3] + bv1;
            if (do_phi) {
                v0 = (v0 > 0.f) ? (v0 + 1.f) : __expf(v0);
                v1 = (v1 > 0.f) ? (v1 + 1.f) : __expf(v1);
                v2 = (v2 > 0.f) ? (v2 + 1.f) : __expf(v2);
                v3 = (v3 > 0.f) ? (v3 + 1.f) : __expf(v3);
            }
            if (Ch) {
                __half2 a = __floats2half2_rn(v0, v1);
                __half2 b = __floats2half2_rn(v2, v3);
                *(__half2*)&Ch[(size_t)row * DDIM + col]       = a;
                *(__half2*)&Ch[(size_t)(row + 8) * DDIM + col] = b;
            } else {
                *(float2*)&Cf[(size_t)row * DDIM + col]       = make_float2(v0, v1);
                *(float2*)&Cf[(size_t)(row + 8) * DDIM + col] = make_float2(v2, v3);
            }
        }
    }
}

// ---------------- KV = K^T V per (b,h): fp16 inputs, fp32 SIMT compute ----------------
__global__ __launch_bounds__(256)
void kv_part_kernel()
{
    const int bh = blockIdx.x;
    const int part = blockIdx.y;
    const int b = bh >> 4, h = bh & 15;
    const int sbeg = part * (SSEQ / NPART), send = sbeg + (SSEQ / NPART);

    const __half* Kp = g_Kh + (size_t)b * SSEQ * DDIM + h * DK;
    const __half* Vp = g_Vh + (size_t)b * SSEQ * DDIM + h * DK;

    __shared__ float Ks[32][DK];
    __shared__ float Vs[32][DK];

    const int tid = threadIdx.x;
    const int lr = tid >> 3;      // 0..31 : row
    const int lc = tid & 7;       // 0..7  : 8-half group
    const int tx = tid & 15, ty = tid >> 4;
    const int d0 = ty * 4, e0 = tx * 4;

    float acc[4][4];
#pragma unroll
    for (int i = 0; i < 4; i++)
#pragma unroll
        for (int j = 0; j < 4; j++) acc[i][j] = 0.f;
    float ks = 0.f;

    for (int s0 = sbeg; s0 < send; s0 += 32) {
        // load 32 rows x 64 halfs per tensor; one uint4 (8 halfs) per thread
        {
            uint4 kr = *(const uint4*)&Kp[(size_t)(s0 + lr) * DDIM + lc * 8];
            uint4 vr = *(const uint4*)&Vp[(size_t)(s0 + lr) * DDIM + lc * 8];
            float2 k0 = __half22float2(*(__half2*)&kr.x);
            float2 k1 = __half22float2(*(__half2*)&kr.y);
            float2 k2 = __half22float2(*(__half2*)&kr.z);
            float2 k3 = __half22float2(*(__half2*)&kr.w);
            *(float4*)&Ks[lr][lc * 8]     = make_float4(k0.x, k0.y, k1.x, k1.y);
            *(float4*)&Ks[lr][lc * 8 + 4] = make_float4(k2.x, k2.y, k3.x, k3.y);
            float2 v0 = __half22float2(*(__half2*)&vr.x);
            float2 v1 = __half22float2(*(__half2*)&vr.y);
            float2 v2 = __half22float2(*(__half2*)&vr.z);
            float2 v3 = __half22float2(*(__half2*)&vr.w);
            *(float4*)&Vs[lr][lc * 8]     = make_float4(v0.x, v0.y, v1.x, v1.y);
            *(float4*)&Vs[lr][lc * 8 + 4] = make_float4(v2.x, v2.y, v3.x, v3.y);
        }
        __syncthreads();

#pragma unroll
        for (int s = 0; s < 32; s++) {
            float4 kk = *(const float4*)&Ks[s][d0];
            float4 vv = *(const float4*)&Vs[s][e0];
            float kr[4] = {kk.x, kk.y, kk.z, kk.w};
            float vr[4] = {vv.x, vv.y, vv.z, vv.w};
#pragma unroll
            for (int i = 0; i < 4; i++)
#pragma unroll
                for (int j = 0; j < 4; j++) acc[i][j] += kr[i] * vr[j];
        }
        if (tid < DK) {
#pragma unroll
            for (int s = 0; s < 32; s++) ks += Ks[s][tid];
        }
        __syncthreads();
    }

    float* out = g_KVp[part] + (size_t)bh * DK * DK;
#pragma unroll
    for (int i = 0; i < 4; i++)
#pragma unroll
        for (int j = 0; j < 4; j++) out[(d0 + i) * DK + e0 + j] = acc[i][j];
    if (tid < DK) g_Ksp[part][bh * DK + tid] = ks;
}

// ---------------- reduce partials -> KVh (transposed [e][d], fp16) + Ksum fp32 ----------------
__global__ __launch_bounds__(256)
void kv_reduce_kernel()
{
    const int bh = blockIdx.x;
    const int tid = threadIdx.x;
    const size_t base = (size_t)bh * DK * DK;
    for (int i = tid; i < DK * DK; i += 256) {
        float s = 0.f;
#pragma unroll
        for (int p = 0; p < NPART; p++) s += g_KVp[p][base + i];
        const int d = i >> 6, e = i & 63;
        g_KVh[base + (size_t)e * DK + d] = __float2half_rn(s);
    }
    if (tid < DK) {
        const int o = bh * DK + tid;
        float s = 0.f;
#pragma unroll
        for (int p = 0; p < NPART; p++) s += g_Ksp[p][o];
        g_Ksum[o] = s;
    }
}

// ---------------- attn: out = (Q·KV)/(Q·Ksum+eps) via fp16 mma ----------------
__global__ __launch_bounds__(256)
void attn_mma_kernel()
{
    __shared__ char qsm[128 * 128];    // Q tile fp16: 128 rows x 128B (swizzled)
    __shared__ char kvsm[64 * 128];    // KVT fp16: 64 e-rows x 128B (swizzled)
    __shared__ float Ksm[DK];
    __shared__ float zs[128];
    const uint32_t q_u = smem_u32(qsm);
    const uint32_t kv_u = smem_u32(kvsm);

    const int bh = blockIdx.y;
    const int b = bh >> 4, h = bh & 15;
    const int s_base = blockIdx.x * 128;

    const __half* Qp  = g_Qh + (size_t)b * SSEQ * DDIM + h * DK;
    const __half* KVp = g_KVh + (size_t)bh * DK * DK;
    __half* Op        = g_Ah + (size_t)b * SSEQ * DDIM + h * DK;

    const int tid = threadIdx.x;
    const int wid = tid >> 5, lane = tid & 31;

#pragma unroll
    for (int i = 0; i < 4; i++) {
        int idx = tid + i * 256;
        int r = idx >> 3, c = idx & 7;
        int cs = c ^ (r & 7);
        cp16(q_u + (uint32_t)(r * 128 + cs * 16),
             &Qp[(size_t)(s_base + r) * DDIM + c * 8]);
    }
#pragma unroll
    for (int i = 0; i < 2; i++) {
        int idx = tid + i * 256;
        int r = idx >> 3, c = idx & 7;
        int cs = c ^ (r & 7);
        cp16(kv_u + (uint32_t)(r * 128 + cs * 16), &KVp[(size_t)r * DK + c * 8]);
    }
    if (tid < DK) Ksm[tid] = g_Ksum[bh * DK + tid];
    asm volatile("cp.async.commit_group;" ::: "memory");
    asm volatile("cp.async.wait_group 0;" ::: "memory");
    __syncthreads();

    // z per row (threads 0-127)
    if (tid < 128) {
        const int r = tid;
        float z = 0.f;
#pragma unroll
        for (int d = 0; d < DK; d++) {
            __half hv = *(const __half*)(qsm + r * 128 + (((d >> 3) ^ (r & 7)) * 16) + (d & 7) * 2);
            z += __half2float(hv) * Ksm[d];
        }
        zs[r] = 1.f / (z + 1e-6f);
    }

    const int wm = wid * 16;
    float acc[8][4];
#pragma unroll
    for (int j = 0; j < 8; j++)
#pragma unroll
        for (int q = 0; q < 4; q++) acc[j][q] = 0.f;

#pragma unroll
    for (int ks = 0; ks < 4; ks++) {
        uint32_t af[4];
        {
            const int r = lane & 15, sel = lane >> 4;
            const int row = wm + r;
            const int ch = (ks * 2 + sel) ^ (row & 7);
            ldm_x4(af, q_u + row * 128 + ch * 16);
        }
        uint32_t bf[4][4];
        {
            const int g = lane >> 3, rr = lane & 7;
#pragma unroll
            for (int p = 0; p < 4; p++) {
                const int row = p * 16 + (g >> 1) * 8 + rr;
                const int ch = (ks * 2 + (g & 1)) ^ (row & 7);
                ldm_x4(bf[p], kv_u + row * 128 + ch * 16);
            }
        }
#pragma unroll
        for (int p = 0; p < 4; p++) {
            mma_f16(acc[2*p][0], acc[2*p][1], acc[2*p][2], acc[2*p][3],
                    af[0], af[1], af[2], af[3], bf[p][0], bf[p][1]);
            mma_f16(acc[2*p+1][0], acc[2*p+1][1], acc[2*p+1][2], acc[2*p+1][3],
                    af[0], af[1], af[2], af[3], bf[p][2], bf[p][3]);
        }
    }
    __syncthreads();

    const int tr = lane >> 2, tc = lane & 3;
    const float iz0 = zs[wm + tr], iz1 = zs[wm + tr + 8];
#pragma unroll
    for (int nt = 0; nt < 8; nt++) {
        const int e = nt * 8 + tc * 2;
        __half2 o0 = __floats2half2_rn(acc[nt][0] * iz0, acc[nt][1] * iz0);
        __half2 o1 = __floats2half2_rn(acc[nt][2] * iz1, acc[nt][3] * iz1);
        *(__half2*)&Op[(size_t)(s_base + wm + tr) * DDIM + e]     = o0;
        *(__half2*)&Op[(size_t)(s_base + wm + tr + 8) * DDIM + e] = o1;
    }
}

// ---------------- host ----------------
extern "C" void kernel_launch(void* const* d_in, const int* in_sizes, int n_in,
                              void* d_out, int out_size)
{
    const float* x  = (const float*)d_in[0];
    const float* Wq = (const float*)d_in[1];
    const float* bq = (const float*)d_in[2];
    const float* Wk = (const float*)d_in[3];
    const float* bk = (const float*)d_in[4];
    const float* Wv = (const float*)d_in[5];
    const float* bv = (const float*)d_in[6];
    const float* Wo = (const float*)d_in[7];
    const float* bo = (const float*)d_in[8];

    __half *Xh, *Qh, *Kh, *Vh, *Ah, *Wh;
    cudaGetSymbolAddress((void**)&Xh, g_Xh);
    cudaGetSymbolAddress((void**)&Qh, g_Qh);
    cudaGetSymbolAddress((void**)&Kh, g_Kh);
    cudaGetSymbolAddress((void**)&Vh, g_Vh);
    cudaGetSymbolAddress((void**)&Ah, g_Ah);
    cudaGetSymbolAddress((void**)&Wh, g_Wh);

    __half* Whq = Wh;
    __half* Whk = Wh + (size_t)DDIM * DDIM;
    __half* Whv = Wh + 2 * (size_t)DDIM * DDIM;
    __half* Who = Wh + 3 * (size_t)DDIM * DDIM;

    cudaFuncSetAttribute(gemm_h, cudaFuncAttributeMaxDynamicSharedMemorySize, GEMM_SMEM);

    const int NX = MTOT * DDIM;
    const int NW = DDIM * DDIM;
    f2h_kernel<<<NX / 8 / 256, 256>>>(x, Xh, NX);
    f2h_kernel<<<NW / 8 / 256, 256>>>(Wq, Whq, NW);
    f2h_kernel<<<NW / 8 / 256, 256>>>(Wk, Whk, NW);
    f2h_kernel<<<NW / 8 / 256, 256>>>(Wv, Whv, NW);
    f2h_kernel<<<NW / 8 / 256, 256>>>(Wo, Who, NW);

    dim3 gg(DDIM / BNg, MTOT / BMg);
    gemm_h<<<gg, 256, GEMM_SMEM>>>(Xh, Whk, bk, nullptr, Kh, 1);
    gemm_h<<<gg, 256, GEMM_SMEM>>>(Xh, Whv, bv, nullptr, Vh, 0);
    gemm_h<<<gg, 256, GEMM_SMEM>>>(Xh, Whq, bq, nullptr, Qh, 1);

    kv_part_kernel<<<dim3(BB * HH, NPART), 256>>>();
    kv_reduce_kernel<<<BB * HH, 256>>>();
    attn_mma_kernel<<<dim3(SSEQ / 128, BB * HH), 256>>>();

    gemm_h<<<gg, 256, GEMM_SMEM>>>(Ah, Who, bo, (float*)d_out, nullptr, 0);
}

// round 13
// speedup vs baseline: 8.9015x; 1.1070x over previous
#include <cuda_runtime.h>
#include <cuda_fp16.h>
#include <cstdint>
#include <math.h>

#define MTOT 32768   // B*S
#define DDIM 1024
#define SSEQ 4096
#define BB   8
#define HH   16
#define DK   64
#define NPART 16

// ---------------- scratch (no cudaMalloc allowed) ----------------
__device__ __half g_Xh[MTOT * DDIM];
__device__ __half g_QKVh[3][MTOT * DDIM];   // [0]=Q, [1]=K, [2]=V (contiguous)
__device__ __half g_Ah[MTOT * DDIM];
__device__ __half g_Wh[4][DDIM * DDIM];     // Wq,Wk,Wv contiguous + Wo
__device__ float  g_b3[3 * DDIM];
__device__ float  g_KVp[NPART][BB * HH * DK * DK];
__device__ float  g_Ksp[NPART][BB * HH * DK];
__device__ __half g_KVh[BB * HH * DK * DK]; // transposed: [bh][e][d]
__device__ float  g_Ksum[BB * HH * DK];

// ---------------- helpers ----------------
__device__ __forceinline__ uint32_t smem_u32(const void* p) {
    uint32_t a;
    asm("{ .reg .u64 t; cvta.to.shared.u64 t, %1; cvt.u32.u64 %0, t; }" : "=r"(a) : "l"(p));
    return a;
}
__device__ __forceinline__ void cp16(uint32_t dst, const void* src) {
    asm volatile("cp.async.cg.shared.global [%0], [%1], 16;" :: "r"(dst), "l"(src));
}
__device__ __forceinline__ void ldm_x4(uint32_t* r, uint32_t addr) {
    asm volatile("ldmatrix.sync.aligned.m8n8.x4.shared.b16 {%0,%1,%2,%3}, [%4];"
                 : "=r"(r[0]), "=r"(r[1]), "=r"(r[2]), "=r"(r[3]) : "r"(addr));
}
__device__ __forceinline__ void mma_f16(float& d0, float& d1, float& d2, float& d3,
                                        uint32_t a0, uint32_t a1, uint32_t a2, uint32_t a3,
                                        uint32_t b0, uint32_t b1) {
    asm volatile(
        "mma.sync.aligned.m16n8k16.row.col.f32.f16.f16.f32 "
        "{%0,%1,%2,%3},{%4,%5,%6,%7},{%8,%9},{%0,%1,%2,%3};"
        : "+f"(d0), "+f"(d1), "+f"(d2), "+f"(d3)
        : "r"(a0), "r"(a1), "r"(a2), "r"(a3), "r"(b0), "r"(b1));
}

// ---------------- fp32 -> fp16 ----------------
__global__ __launch_bounds__(256)
void f2h_kernel(const float* __restrict__ in, __half* __restrict__ out, int n)
{
    int i = (blockIdx.x * 256 + threadIdx.x) * 8;
    if (i < n) {
        float4 v0 = *(const float4*)(in + i);
        float4 v1 = *(const float4*)(in + i + 4);
        __half2 h0 = __floats2half2_rn(v0.x, v0.y);
        __half2 h1 = __floats2half2_rn(v0.z, v0.w);
        __half2 h2 = __floats2half2_rn(v1.x, v1.y);
        __half2 h3 = __floats2half2_rn(v1.z, v1.w);
        uint4 o;
        o.x = *(uint32_t*)&h0; o.y = *(uint32_t*)&h1;
        o.z = *(uint32_t*)&h2; o.w = *(uint32_t*)&h3;
        *(uint4*)(out + i) = o;
    }
}

// ---------------- shared GEMM core config ----------------
#define BMg 128
#define BNg 128
#define BKh 64
#define NSTG 3
#define ASTG (128 * 128)
#define GEMM_SMEM (2 * NSTG * ASTG)   // 98304

// ---------------- fused QKV GEMM: C[:,0:3072] = Xh * [Wq;Wk;Wv]^T + b3; phi on col<2048 ----------------
__global__ void __launch_bounds__(256, 2) gemm_qkv(
    const __half* __restrict__ A, const __half* __restrict__ W,
    const float* __restrict__ bias, __half* __restrict__ Cbase)
{
    extern __shared__ char smraw[];
    const uint32_t as_u = smem_u32(smraw);
    const uint32_t bs_u = as_u + NSTG * ASTG;

    const int tid = threadIdx.x;
    const int wid = tid >> 5, lane = tid & 31;
    const int tr = lane >> 2, tc = lane & 3;
    const int m0 = blockIdx.y * BMg, n0 = blockIdx.x * BNg;
    const int wm = (wid & 3) * 32, wn = (wid >> 2) * 64;

    float acc[2][8][4];
#pragma unroll
    for (int i = 0; i < 2; i++)
#pragma unroll
        for (int j = 0; j < 8; j++)
#pragma unroll
            for (int q = 0; q < 4; q++) acc[i][j][q] = 0.f;

    auto load_stage = [&](int s, int k0) {
#pragma unroll
        for (int i = 0; i < 4; i++) {
            int idx = tid + i * 256;
            int r = idx >> 3, c = idx & 7;
            int cs = c ^ (r & 7);
            cp16(as_u + (uint32_t)(s * ASTG + r * 128 + cs * 16),
                 &A[(size_t)(m0 + r) * DDIM + k0 + c * 8]);
            cp16(bs_u + (uint32_t)(s * ASTG + r * 128 + cs * 16),
                 &W[(size_t)(n0 + r) * DDIM + k0 + c * 8]);
        }
        asm volatile("cp.async.commit_group;" ::: "memory");
    };

#pragma unroll
    for (int s = 0; s < NSTG; s++) load_stage(s, s * BKh);

    const int NCHUNK = DDIM / BKh;
#pragma unroll 1
    for (int ck = 0; ck < NCHUNK; ck++) {
        const int s = ck % NSTG;
        asm volatile("cp.async.wait_group %0;" :: "n"(NSTG - 1) : "memory");
        __syncthreads();

        const uint32_t ab = as_u + s * ASTG;
        const uint32_t bb = bs_u + s * ASTG;
#pragma unroll
        for (int ks = 0; ks < 4; ks++) {
            uint32_t af[2][4];
            {
                const int r = lane & 15, sel = lane >> 4;
#pragma unroll
                for (int mt = 0; mt < 2; mt++) {
                    const int row = wm + mt * 16 + r;
                    const int ch = (ks * 2 + sel) ^ (row & 7);
                    ldm_x4(af[mt], ab + row * 128 + ch * 16);
                }
            }
            uint32_t bf[4][4];
            {
                const int g = lane >> 3, rr = lane & 7;
#pragma unroll
                for (int p = 0; p < 4; p++) {
                    const int row = wn + p * 16 + (g >> 1) * 8 + rr;
                    const int ch = (ks * 2 + (g & 1)) ^ (row & 7);
                    ldm_x4(bf[p], bb + row * 128 + ch * 16);
                }
            }
#pragma unroll
            for (int mt = 0; mt < 2; mt++)
#pragma unroll
                for (int p = 0; p < 4; p++) {
                    mma_f16(acc[mt][2*p][0], acc[mt][2*p][1], acc[mt][2*p][2], acc[mt][2*p][3],
                            af[mt][0], af[mt][1], af[mt][2], af[mt][3],
                            bf[p][0], bf[p][1]);
                    mma_f16(acc[mt][2*p+1][0], acc[mt][2*p+1][1], acc[mt][2*p+1][2], acc[mt][2*p+1][3],
                            af[mt][0], af[mt][1], af[mt][2], af[mt][3],
                            bf[p][2], bf[p][3]);
                }
        }
        __syncthreads();
        if (ck + NSTG < NCHUNK) load_stage(s, (ck + NSTG) * BKh);
    }

#pragma unroll
    for (int mt = 0; mt < 2; mt++) {
        const int row = m0 + wm + mt * 16 + tr;
#pragma unroll
        for (int nt = 0; nt < 8; nt++) {
            const int col = n0 + wn + nt * 8 + tc * 2;
            const float bv0 = __ldg(&bias[col]), bv1 = __ldg(&bias[col + 1]);
            float v0 = acc[mt][nt][0] + bv0;
            float v1 = acc[mt][nt][1] + bv1;
            float v2 = acc[mt][nt][2] + bv0;
            float v3 = acc[mt][nt][3] + bv1;
            if (col < 2048) {
                v0 = (v0 > 0.f) ? (v0 + 1.f) : __expf(v0);
                v1 = (v1 > 0.f) ? (v1 + 1.f) : __expf(v1);
                v2 = (v2 > 0.f) ? (v2 + 1.f) : __expf(v2);
                v3 = (v3 > 0.f) ? (v3 + 1.f) : __expf(v3);
            }
            const int t = col >> 10, c = col & 1023;
            __half* Ch = Cbase + (size_t)t * (MTOT * DDIM);
            __half2 a = __floats2half2_rn(v0, v1);
            __half2 b = __floats2half2_rn(v2, v3);
            *(__half2*)&Ch[(size_t)row * DDIM + c]       = a;
            *(__half2*)&Ch[(size_t)(row + 8) * DDIM + c] = b;
        }
    }
}

// ---------------- O GEMM: fp16 in, fp32 out ----------------
__global__ void __launch_bounds__(256, 2) gemm_h(
    const __half* __restrict__ A, const __half* __restrict__ W,
    const float* __restrict__ bias, float* __restrict__ Cf)
{
    extern __shared__ char smraw[];
    const uint32_t as_u = smem_u32(smraw);
    const uint32_t bs_u = as_u + NSTG * ASTG;

    const int tid = threadIdx.x;
    const int wid = tid >> 5, lane = tid & 31;
    const int tr = lane >> 2, tc = lane & 3;
    const int m0 = blockIdx.y * BMg, n0 = blockIdx.x * BNg;
    const int wm = (wid & 3) * 32, wn = (wid >> 2) * 64;

    float acc[2][8][4];
#pragma unroll
    for (int i = 0; i < 2; i++)
#pragma unroll
        for (int j = 0; j < 8; j++)
#pragma unroll
            for (int q = 0; q < 4; q++) acc[i][j][q] = 0.f;

    auto load_stage = [&](int s, int k0) {
#pragma unroll
        for (int i = 0; i < 4; i++) {
            int idx = tid + i * 256;
            int r = idx >> 3, c = idx & 7;
            int cs = c ^ (r & 7);
            cp16(as_u + (uint32_t)(s * ASTG + r * 128 + cs * 16),
                 &A[(size_t)(m0 + r) * DDIM + k0 + c * 8]);
            cp16(bs_u + (uint32_t)(s * ASTG + r * 128 + cs * 16),
                 &W[(size_t)(n0 + r) * DDIM + k0 + c * 8]);
        }
        asm volatile("cp.async.commit_group;" ::: "memory");
    };

#pragma unroll
    for (int s = 0; s < NSTG; s++) load_stage(s, s * BKh);

    const int NCHUNK = DDIM / BKh;
#pragma unroll 1
    for (int ck = 0; ck < NCHUNK; ck++) {
        const int s = ck % NSTG;
        asm volatile("cp.async.wait_group %0;" :: "n"(NSTG - 1) : "memory");
        __syncthreads();

        const uint32_t ab = as_u + s * ASTG;
        const uint32_t bb = bs_u + s * ASTG;
#pragma unroll
        for (int ks = 0; ks < 4; ks++) {
            uint32_t af[2][4];
            {
                const int r = lane & 15, sel = lane >> 4;
#pragma unroll
                for (int mt = 0; mt < 2; mt++) {
                    const int row = wm + mt * 16 + r;
                    const int ch = (ks * 2 + sel) ^ (row & 7);
                    ldm_x4(af[mt], ab + row * 128 + ch * 16);
                }
            }
            uint32_t bf[4][4];
            {
                const int g = lane >> 3, rr = lane & 7;
#pragma unroll
                for (int p = 0; p < 4; p++) {
                    const int row = wn + p * 16 + (g >> 1) * 8 + rr;
                    const int ch = (ks * 2 + (g & 1)) ^ (row & 7);
                    ldm_x4(bf[p], bb + row * 128 + ch * 16);
                }
            }
#pragma unroll
            for (int mt = 0; mt < 2; mt++)
#pragma unroll
                for (int p = 0; p < 4; p++) {
                    mma_f16(acc[mt][2*p][0], acc[mt][2*p][1], acc[mt][2*p][2], acc[mt][2*p][3],
                            af[mt][0], af[mt][1], af[mt][2], af[mt][3],
                            bf[p][0], bf[p][1]);
                    mma_f16(acc[mt][2*p+1][0], acc[mt][2*p+1][1], acc[mt][2*p+1][2], acc[mt][2*p+1][3],
                            af[mt][0], af[mt][1], af[mt][2], af[mt][3],
                            bf[p][2], bf[p][3]);
                }
        }
        __syncthreads();
        if (ck + NSTG < NCHUNK) load_stage(s, (ck + NSTG) * BKh);
    }

#pragma unroll
    for (int mt = 0; mt < 2; mt++) {
        const int row = m0 + wm + mt * 16 + tr;
#pragma unroll
        for (int nt = 0; nt < 8; nt++) {
            const int col = n0 + wn + nt * 8 + tc * 2;
            const float bv0 = __ldg(&bias[col]), bv1 = __ldg(&bias[col + 1]);
            *(float2*)&Cf[(size_t)row * DDIM + col] =
                make_float2(acc[mt][nt][0] + bv0, acc[mt][nt][1] + bv1);
            *(float2*)&Cf[(size_t)(row + 8) * DDIM + col] =
                make_float2(acc[mt][nt][2] + bv0, acc[mt][nt][3] + bv1);
        }
    }
}

// ---------------- KV = K^T V via smem-transpose + fp16 mma ----------------
// per (bh,part): 256 s in 8 tiles of 32; Kt/Vt transposed to [64 d|e][32 s], row stride 40 halfs.
#define TSTRIDE 40

__global__ __launch_bounds__(256)
void kv_mma2_kernel()
{
    __shared__ __half Kt[64 * TSTRIDE];
    __shared__ __half Vt[64 * TSTRIDE];
    const uint32_t kt_u = smem_u32(Kt), vt_u = smem_u32(Vt);

    const int bh = blockIdx.x, part = blockIdx.y;
    const int b = bh >> 4, h = bh & 15;
    const int sbeg = part * (SSEQ / NPART);   // 256 s per part

    const __half* Kp = g_QKVh[1] + (size_t)b * SSEQ * DDIM + h * DK;
    const __half* Vp = g_QKVh[2] + (size_t)b * SSEQ * DDIM + h * DK;

    const int tid = threadIdx.x;
    const int wid = tid >> 5, lane = tid & 31;
    const int ls = tid & 31;          // s index within tile
    const int d0 = (tid >> 5) * 8;    // this warp's 8-d slice (for loads/Ksum)
    const int wm = (wid & 3) * 16;    // mma d tile
    const int wn = (wid >> 2) * 32;   // mma e tile

    float acc[4][4];
#pragma unroll
    for (int n = 0; n < 4; n++)
#pragma unroll
        for (int q = 0; q < 4; q++) acc[n][q] = 0.f;
    float ksp[8];
#pragma unroll
    for (int j = 0; j < 8; j++) ksp[j] = 0.f;

#pragma unroll 1
    for (int t = 0; t < 8; t++) {
        const int s0 = sbeg + t * 32;
        // load one 16B chunk (8 d) of one s-row per tensor, transpose into smem
        uint4 k8 = *(const uint4*)&Kp[(size_t)(s0 + ls) * DDIM + d0];
        uint4 v8 = *(const uint4*)&Vp[(size_t)(s0 + ls) * DDIM + d0];
        const __half* kh = (const __half*)&k8;
        const __half* vh = (const __half*)&v8;
#pragma unroll
        for (int j = 0; j < 8; j++) {
            Kt[(d0 + j) * TSTRIDE + ls] = kh[j];
            Vt[(d0 + j) * TSTRIDE + ls] = vh[j];
            ksp[j] += __half2float(kh[j]);
        }
        __syncthreads();

        // mma: 2 ksteps of 16 s; fragment pattern identical to gemm core
#pragma unroll
        for (int kk = 0; kk < 2; kk++) {
            uint32_t af[4];
            {
                const int r = lane & 15, sel = lane >> 4;
                const int row = wm + r;
                ldm_x4(af, kt_u + (uint32_t)((row * TSTRIDE + (kk * 2 + sel) * 8) * 2));
            }
            uint32_t bf[2][4];
            {
                const int g = lane >> 3, rr = lane & 7;
#pragma unroll
                for (int p = 0; p < 2; p++) {
                    const int row = wn + p * 16 + (g >> 1) * 8 + rr;
                    ldm_x4(bf[p], vt_u + (uint32_t)((row * TSTRIDE + (kk * 2 + (g & 1)) * 8) * 2));
                }
            }
#pragma unroll
            for (int p = 0; p < 2; p++) {
                mma_f16(acc[2*p][0], acc[2*p][1], acc[2*p][2], acc[2*p][3],
                        af[0], af[1], af[2], af[3], bf[p][0], bf[p][1]);
                mma_f16(acc[2*p+1][0], acc[2*p+1][1], acc[2*p+1][2], acc[2*p+1][3],
                        af[0], af[1], af[2], af[3], bf[p][2], bf[p][3]);
            }
        }
        __syncthreads();
    }

    // write KV partials
    const int tr = lane >> 2, tc = lane & 3;
    float* out = g_KVp[part] + (size_t)bh * DK * DK;
#pragma unroll
    for (int nt = 0; nt < 4; nt++) {
        const int e = wn + nt * 8 + tc * 2;
        *(float2*)&out[(wm + tr) * DK + e]     = make_float2(acc[nt][0], acc[nt][1]);
        *(float2*)&out[(wm + tr + 8) * DK + e] = make_float2(acc[nt][2], acc[nt][3]);
    }
    // Ksum: reduce each warp's 8 d-partials over its 32 s-lanes
#pragma unroll
    for (int j = 0; j < 8; j++) {
#pragma unroll
        for (int off = 16; off > 0; off >>= 1)
            ksp[j] += __shfl_xor_sync(0xFFFFFFFF, ksp[j], off);
    }
    if (lane == 0) {
#pragma unroll
        for (int j = 0; j < 8; j++)
            g_Ksp[part][bh * DK + d0 + j] = ksp[j];
    }
}

// ---------------- reduce partials -> KVh (transposed [e][d], fp16) + Ksum fp32 ----------------
__global__ __launch_bounds__(256)
void kv_reduce_kernel()
{
    const int bh = blockIdx.x;
    const int tid = threadIdx.x;
    const size_t base = (size_t)bh * DK * DK;
    for (int i = tid; i < DK * DK; i += 256) {
        float s = 0.f;
#pragma unroll
        for (int p = 0; p < NPART; p++) s += g_KVp[p][base + i];
        const int d = i >> 6, e = i & 63;
        g_KVh[base + (size_t)e * DK + d] = __float2half_rn(s);
    }
    if (tid < DK) {
        const int o = bh * DK + tid;
        float s = 0.f;
#pragma unroll
        for (int p = 0; p < NPART; p++) s += g_Ksp[p][o];
        g_Ksum[o] = s;
    }
}

// ---------------- attn: out = (Q·KV)/(Q·Ksum+eps) via fp16 mma ----------------
__global__ __launch_bounds__(256)
void attn_mma_kernel()
{
    __shared__ char qsm[128 * 128];
    __shared__ char kvsm[64 * 128];
    __shared__ float Ksm[DK];
    __shared__ float zs[128];
    const uint32_t q_u = smem_u32(qsm);
    const uint32_t kv_u = smem_u32(kvsm);

    const int bh = blockIdx.y;
    const int b = bh >> 4, h = bh & 15;
    const int s_base = blockIdx.x * 128;

    const __half* Qp  = g_QKVh[0] + (size_t)b * SSEQ * DDIM + h * DK;
    const __half* KVp = g_KVh + (size_t)bh * DK * DK;
    __half* Op        = g_Ah + (size_t)b * SSEQ * DDIM + h * DK;

    const int tid = threadIdx.x;
    const int wid = tid >> 5, lane = tid & 31;

#pragma unroll
    for (int i = 0; i < 4; i++) {
        int idx = tid + i * 256;
        int r = idx >> 3, c = idx & 7;
        int cs = c ^ (r & 7);
        cp16(q_u + (uint32_t)(r * 128 + cs * 16),
             &Qp[(size_t)(s_base + r) * DDIM + c * 8]);
    }
#pragma unroll
    for (int i = 0; i < 2; i++) {
        int idx = tid + i * 256;
        int r = idx >> 3, c = idx & 7;
        int cs = c ^ (r & 7);
        cp16(kv_u + (uint32_t)(r * 128 + cs * 16), &KVp[(size_t)r * DK + c * 8]);
    }
    if (tid < DK) Ksm[tid] = g_Ksum[bh * DK + tid];
    asm volatile("cp.async.commit_group;" ::: "memory");
    asm volatile("cp.async.wait_group 0;" ::: "memory");
    __syncthreads();

    if (tid < 128) {
        const int r = tid;
        float z = 0.f;
#pragma unroll
        for (int d = 0; d < DK; d++) {
            __half hv = *(const __half*)(qsm + r * 128 + (((d >> 3) ^ (r & 7)) * 16) + (d & 7) * 2);
            z += __half2float(hv) * Ksm[d];
        }
        zs[r] = 1.f / (z + 1e-6f);
    }

    const int wm = wid * 16;
    float acc[8][4];
#pragma unroll
    for (int j = 0; j < 8; j++)
#pragma unroll
        for (int q = 0; q < 4; q++) acc[j][q] = 0.f;

#pragma unroll
    for (int ks = 0; ks < 4; ks++) {
        uint32_t af[4];
        {
            const int r = lane & 15, sel = lane >> 4;
            const int row = wm + r;
            const int ch = (ks * 2 + sel) ^ (row & 7);
            ldm_x4(af, q_u + row * 128 + ch * 16);
        }
        uint32_t bf[4][4];
        {
            const int g = lane >> 3, rr = lane & 7;
#pragma unroll
            for (int p = 0; p < 4; p++) {
                const int row = p * 16 + (g >> 1) * 8 + rr;
                const int ch = (ks * 2 + (g & 1)) ^ (row & 7);
                ldm_x4(bf[p], kv_u + row * 128 + ch * 16);
            }
        }
#pragma unroll
        for (int p = 0; p < 4; p++) {
            mma_f16(acc[2*p][0], acc[2*p][1], acc[2*p][2], acc[2*p][3],
                    af[0], af[1], af[2], af[3], bf[p][0], bf[p][1]);
            mma_f16(acc[2*p+1][0], acc[2*p+1][1], acc[2*p+1][2], acc[2*p+1][3],
                    af[0], af[1], af[2], af[3], bf[p][2], bf[p][3]);
        }
    }
    __syncthreads();

    const int tr = lane >> 2, tc = lane & 3;
    const float iz0 = zs[wm + tr], iz1 = zs[wm + tr + 8];
#pragma unroll
    for (int nt = 0; nt < 8; nt++) {
        const int e = nt * 8 + tc * 2;
        __half2 o0 = __floats2half2_rn(acc[nt][0] * iz0, acc[nt][1] * iz0);
        __half2 o1 = __floats2half2_rn(acc[nt][2] * iz1, acc[nt][3] * iz1);
        *(__half2*)&Op[(size_t)(s_base + wm + tr) * DDIM + e]     = o0;
        *(__half2*)&Op[(size_t)(s_base + wm + tr + 8) * DDIM + e] = o1;
    }
}

// ---------------- host ----------------
extern "C" void kernel_launch(void* const* d_in, const int* in_sizes, int n_in,
                              void* d_out, int out_size)
{
    const float* x  = (const float*)d_in[0];
    const float* Wq = (const float*)d_in[1];
    const float* bq = (const float*)d_in[2];
    const float* Wk = (const float*)d_in[3];
    const float* bk = (const float*)d_in[4];
    const float* Wv = (const float*)d_in[5];
    const float* bv = (const float*)d_in[6];
    const float* Wo = (const float*)d_in[7];
    const float* bo = (const float*)d_in[8];

    __half *Xh, *QKVh, *Ah, *Wh;
    float* b3;
    cudaGetSymbolAddress((void**)&Xh, g_Xh);
    cudaGetSymbolAddress((void**)&QKVh, g_QKVh);
    cudaGetSymbolAddress((void**)&Ah, g_Ah);
    cudaGetSymbolAddress((void**)&Wh, g_Wh);
    cudaGetSymbolAddress((void**)&b3, g_b3);

    __half* Whq = Wh;
    __half* Whk = Wh + (size_t)DDIM * DDIM;
    __half* Whv = Wh + 2 * (size_t)DDIM * DDIM;
    __half* Who = Wh + 3 * (size_t)DDIM * DDIM;

    cudaFuncSetAttribute(gemm_qkv, cudaFuncAttributeMaxDynamicSharedMemorySize, GEMM_SMEM);
    cudaFuncSetAttribute(gemm_h,   cudaFuncAttributeMaxDynamicSharedMemorySize, GEMM_SMEM);

    const int NX = MTOT * DDIM;
    const int NW = DDIM * DDIM;
    f2h_kernel<<<NX / 8 / 256, 256>>>(x, Xh, NX);
    f2h_kernel<<<NW / 8 / 256, 256>>>(Wq, Whq, NW);
    f2h_kernel<<<NW / 8 / 256, 256>>>(Wk, Whk, NW);
    f2h_kernel<<<NW / 8 / 256, 256>>>(Wv, Whv, NW);
    f2h_kernel<<<NW / 8 / 256, 256>>>(Wo, Who, NW);
    cudaMemcpyAsync(b3,            bq, DDIM * sizeof(float), cudaMemcpyDeviceToDevice);
    cudaMemcpyAsync(b3 + DDIM,     bk, DDIM * sizeof(float), cudaMemcpyDeviceToDevice);
    cudaMemcpyAsync(b3 + 2 * DDIM, bv, DDIM * sizeof(float), cudaMemcpyDeviceToDevice);

    gemm_qkv<<<dim3(3 * DDIM / BNg, MTOT / BMg), 256, GEMM_SMEM>>>(Xh, Whq, b3, QKVh);

    kv_mma2_kernel<<<dim3(BB * HH, NPART), 256>>>();
    kv_reduce_kernel<<<BB * HH, 256>>>();
    attn_mma_kernel<<<dim3(SSEQ / 128, BB * HH), 256>>>();

    gemm_h<<<dim3(DDIM / BNg, MTOT / BMg), 256, GEMM_SMEM>>>(Ah, Who, bo, (float*)d_out);
}

// round 17
// speedup vs baseline: 8.9923x; 1.0102x over previous
#include <cuda_runtime.h>
#include <cuda_fp16.h>
#include <cstdint>
#include <math.h>

#define MTOT 32768   // B*S
#define DDIM 1024
#define SSEQ 4096
#define BB   8
#define HH   16
#define DK   64
#define NPART 16

// ---------------- scratch (no cudaMalloc allowed) ----------------
__device__ __half g_Xh[MTOT * DDIM];
__device__ __half g_QKVh[3][MTOT * DDIM];   // [0]=Q, [1]=K, [2]=V (contiguous)
__device__ __half g_Ah[MTOT * DDIM];
__device__ __half g_Wh[4][DDIM * DDIM];     // Wq,Wk,Wv contiguous + Wo
__device__ float  g_b3[3 * DDIM];
__device__ float  g_KVp[NPART][BB * HH * DK * DK];
__device__ float  g_Ksp[NPART][BB * HH * DK];
__device__ __half g_KVh[BB * HH * DK * DK]; // transposed: [bh][e][d]
__device__ float  g_Ksum[BB * HH * DK];

// ---------------- helpers ----------------
__device__ __forceinline__ uint32_t smem_u32(const void* p) {
    uint32_t a;
    asm("{ .reg .u64 t; cvta.to.shared.u64 t, %1; cvt.u32.u64 %0, t; }" : "=r"(a) : "l"(p));
    return a;
}
__device__ __forceinline__ void cp16(uint32_t dst, const void* src) {
    asm volatile("cp.async.cg.shared.global [%0], [%1], 16;" :: "r"(dst), "l"(src));
}
__device__ __forceinline__ void ldm_x4(uint32_t* r, uint32_t addr) {
    asm volatile("ldmatrix.sync.aligned.m8n8.x4.shared.b16 {%0,%1,%2,%3}, [%4];"
                 : "=r"(r[0]), "=r"(r[1]), "=r"(r[2]), "=r"(r[3]) : "r"(addr));
}
__device__ __forceinline__ void mma_f16(float& d0, float& d1, float& d2, float& d3,
                                        uint32_t a0, uint32_t a1, uint32_t a2, uint32_t a3,
                                        uint32_t b0, uint32_t b1) {
    asm volatile(
        "mma.sync.aligned.m16n8k16.row.col.f32.f16.f16.f32 "
        "{%0,%1,%2,%3},{%4,%5,%6,%7},{%8,%9},{%0,%1,%2,%3};"
        : "+f"(d0), "+f"(d1), "+f"(d2), "+f"(d3)
        : "r"(a0), "r"(a1), "r"(a2), "r"(a3), "r"(b0), "r"(b1));
}

// ---------------- fused fp32 -> fp16 (all 5 tensors, one launch) ----------------
#define F2H_TPB 256
#define NXB (MTOT * DDIM / 8 / F2H_TPB)     // 16384 blocks
#define NWB (DDIM * DDIM / 8 / F2H_TPB)     // 512 blocks

__global__ __launch_bounds__(F2H_TPB)
void f2h_all_kernel(const float* __restrict__ x,
                    const float* __restrict__ w0, const float* __restrict__ w1,
                    const float* __restrict__ w2, const float* __restrict__ w3,
                    __half* __restrict__ xh, __half* __restrict__ wh)
{
    int blk = blockIdx.x;
    const float* in;
    __half* out;
    int base;
    if (blk < NXB) {
        in = x; out = xh; base = blk;
    } else {
        int wseg = (blk - NXB) / NWB;
        base = (blk - NXB) % NWB;
        in = (wseg == 0) ? w0 : (wseg == 1) ? w1 : (wseg == 2) ? w2 : w3;
        out = wh + (size_t)wseg * (DDIM * DDIM);
    }
    int i = (base * F2H_TPB + threadIdx.x) * 8;
    float4 v0 = *(const float4*)(in + i);
    float4 v1 = *(const float4*)(in + i + 4);
    __half2 h0 = __floats2half2_rn(v0.x, v0.y);
    __half2 h1 = __floats2half2_rn(v0.z, v0.w);
    __half2 h2 = __floats2half2_rn(v1.x, v1.y);
    __half2 h3 = __floats2half2_rn(v1.z, v1.w);
    uint4 o;
    o.x = *(uint32_t*)&h0; o.y = *(uint32_t*)&h1;
    o.z = *(uint32_t*)&h2; o.w = *(uint32_t*)&h3;
    *(uint4*)(out + i) = o;
}

// ---------------- shared GEMM core config ----------------
#define BMg 128
#define BNg 128
#define BKh 64
#define NSTG 3
#define ASTG (128 * 128)
#define GEMM_SMEM (2 * NSTG * ASTG)   // 98304
#define NCHUNK (DDIM / BKh)           // 16

// ---------------- fused QKV GEMM ----------------
__global__ void __launch_bounds__(256, 2) gemm_qkv(
    const __half* __restrict__ A, const __half* __restrict__ W,
    const float* __restrict__ bias, __half* __restrict__ Cbase)
{
    extern __shared__ char smraw[];
    const uint32_t as_u = smem_u32(smraw);
    const uint32_t bs_u = as_u + NSTG * ASTG;

    const int tid = threadIdx.x;
    const int wid = tid >> 5, lane = tid & 31;
    const int tr = lane >> 2, tc = lane & 3;
    const int m0 = blockIdx.y * BMg, n0 = blockIdx.x * BNg;
    const int wm = (wid & 3) * 32, wn = (wid >> 2) * 64;

    float acc[2][8][4];
#pragma unroll
    for (int i = 0; i < 2; i++)
#pragma unroll
        for (int j = 0; j < 8; j++)
#pragma unroll
            for (int q = 0; q < 4; q++) acc[i][j][q] = 0.f;

    auto load_stage = [&](int s, int k0) {
#pragma unroll
        for (int i = 0; i < 4; i++) {
            int idx = tid + i * 256;
            int r = idx >> 3, c = idx & 7;
            int cs = c ^ (r & 7);
            cp16(as_u + (uint32_t)(s * ASTG + r * 128 + cs * 16),
                 &A[(size_t)(m0 + r) * DDIM + k0 + c * 8]);
            cp16(bs_u + (uint32_t)(s * ASTG + r * 128 + cs * 16),
                 &W[(size_t)(n0 + r) * DDIM + k0 + c * 8]);
        }
        asm volatile("cp.async.commit_group;" ::: "memory");
    };

    load_stage(0, 0);
    load_stage(1, BKh);

#pragma unroll 1
    for (int ck = 0; ck < NCHUNK; ck++) {
        const int s = ck % NSTG;
        asm volatile("cp.async.wait_group 1;" ::: "memory");
        __syncthreads();
        const int j = ck + NSTG - 1;
        if (j < NCHUNK) load_stage(j % NSTG, j * BKh);

        const uint32_t ab = as_u + s * ASTG;
        const uint32_t bb = bs_u + s * ASTG;
#pragma unroll
        for (int ks = 0; ks < 4; ks++) {
            uint32_t af[2][4];
            {
                const int r = lane & 15, sel = lane >> 4;
#pragma unroll
                for (int mt = 0; mt < 2; mt++) {
                    const int row = wm + mt * 16 + r;
                    const int ch = (ks * 2 + sel) ^ (row & 7);
                    ldm_x4(af[mt], ab + row * 128 + ch * 16);
                }
            }
            uint32_t bf[4][4];
            {
                const int g = lane >> 3, rr = lane & 7;
#pragma unroll
                for (int p = 0; p < 4; p++) {
                    const int row = wn + p * 16 + (g >> 1) * 8 + rr;
                    const int ch = (ks * 2 + (g & 1)) ^ (row & 7);
                    ldm_x4(bf[p], bb + row * 128 + ch * 16);
                }
            }
#pragma unroll
            for (int mt = 0; mt < 2; mt++)
#pragma unroll
                for (int p = 0; p < 4; p++) {
                    mma_f16(acc[mt][2*p][0], acc[mt][2*p][1], acc[mt][2*p][2], acc[mt][2*p][3],
                            af[mt][0], af[mt][1], af[mt][2], af[mt][3],
                            bf[p][0], bf[p][1]);
                    mma_f16(acc[mt][2*p+1][0], acc[mt][2*p+1][1], acc[mt][2*p+1][2], acc[mt][2*p+1][3],
                            af[mt][0], af[mt][1], af[mt][2], af[mt][3],
                            bf[p][2], bf[p][3]);
                }
        }
    }

#pragma unroll
    for (int mt = 0; mt < 2; mt++) {
        const int row = m0 + wm + mt * 16 + tr;
#pragma unroll
        for (int nt = 0; nt < 8; nt++) {
            const int col = n0 + wn + nt * 8 + tc * 2;
            const float bv0 = __ldg(&bias[col]), bv1 = __ldg(&bias[col + 1]);
            float v0 = acc[mt][nt][0] + bv0;
            float v1 = acc[mt][nt][1] + bv1;
            float v2 = acc[mt][nt][2] + bv0;
            float v3 = acc[mt][nt][3] + bv1;
            if (col < 2048) {
                v0 = (v0 > 0.f) ? (v0 + 1.f) : __expf(v0);
                v1 = (v1 > 0.f) ? (v1 + 1.f) : __expf(v1);
                v2 = (v2 > 0.f) ? (v2 + 1.f) : __expf(v2);
                v3 = (v3 > 0.f) ? (v3 + 1.f) : __expf(v3);
            }
            const int t = col >> 10, c = col & 1023;
            __half* Ch = Cbase + (size_t)t * (MTOT * DDIM);
            __half2 a = __floats2half2_rn(v0, v1);
            __half2 b = __floats2half2_rn(v2, v3);
            *(__half2*)&Ch[(size_t)row * DDIM + c]       = a;
            *(__half2*)&Ch[(size_t)(row + 8) * DDIM + c] = b;
        }
    }
}

// ---------------- O GEMM: fp16 in, fp32 out ----------------
__global__ void __launch_bounds__(256, 2) gemm_h(
    const __half* __restrict__ A, const __half* __restrict__ W,
    const float* __restrict__ bias, float* __restrict__ Cf)
{
    extern __shared__ char smraw[];
    const uint32_t as_u = smem_u32(smraw);
    const uint32_t bs_u = as_u + NSTG * ASTG;

    const int tid = threadIdx.x;
    const int wid = tid >> 5, lane = tid & 31;
    const int tr = lane >> 2, tc = lane & 3;
    const int m0 = blockIdx.y * BMg, n0 = blockIdx.x * BNg;
    const int wm = (wid & 3) * 32, wn = (wid >> 2) * 64;

    float acc[2][8][4];
#pragma unroll
    for (int i = 0; i < 2; i++)
#pragma unroll
        for (int j = 0; j < 8; j++)
#pragma unroll
            for (int q = 0; q < 4; q++) acc[i][j][q] = 0.f;

    auto load_stage = [&](int s, int k0) {
#pragma unroll
        for (int i = 0; i < 4; i++) {
            int idx = tid + i * 256;
            int r = idx >> 3, c = idx & 7;
            int cs = c ^ (r & 7);
            cp16(as_u + (uint32_t)(s * ASTG + r * 128 + cs * 16),
                 &A[(size_t)(m0 + r) * DDIM + k0 + c * 8]);
            cp16(bs_u + (uint32_t)(s * ASTG + r * 128 + cs * 16),
                 &W[(size_t)(n0 + r) * DDIM + k0 + c * 8]);
        }
        asm volatile("cp.async.commit_group;" ::: "memory");
    };

    load_stage(0, 0);
    load_stage(1, BKh);

#pragma unroll 1
    for (int ck = 0; ck < NCHUNK; ck++) {
        const int s = ck % NSTG;
        asm volatile("cp.async.wait_group 1;" ::: "memory");
        __syncthreads();
        const int j = ck + NSTG - 1;
        if (j < NCHUNK) load_stage(j % NSTG, j * BKh);

        const uint32_t ab = as_u + s * ASTG;
        const uint32_t bb = bs_u + s * ASTG;
#pragma unroll
        for (int ks = 0; ks < 4; ks++) {
            uint32_t af[2][4];
            {
                const int r = lane & 15, sel = lane >> 4;
#pragma unroll
                for (int mt = 0; mt < 2; mt++) {
                    const int row = wm + mt * 16 + r;
                    const int ch = (ks * 2 + sel) ^ (row & 7);
                    ldm_x4(af[mt], ab + row * 128 + ch * 16);
                }
            }
            uint32_t bf[4][4];
            {
                const int g = lane >> 3, rr = lane & 7;
#pragma unroll
                for (int p = 0; p < 4; p++) {
                    const int row = wn + p * 16 + (g >> 1) * 8 + rr;
                    const int ch = (ks * 2 + (g & 1)) ^ (row & 7);
                    ldm_x4(bf[p], bb + row * 128 + ch * 16);
                }
            }
#pragma unroll
            for (int mt = 0; mt < 2; mt++)
#pragma unroll
                for (int p = 0; p < 4; p++) {
                    mma_f16(acc[mt][2*p][0], acc[mt][2*p][1], acc[mt][2*p][2], acc[mt][2*p][3],
                            af[mt][0], af[mt][1], af[mt][2], af[mt][3],
                            bf[p][0], bf[p][1]);
                    mma_f16(acc[mt][2*p+1][0], acc[mt][2*p+1][1], acc[mt][2*p+1][2], acc[mt][2*p+1][3],
                            af[mt][0], af[mt][1], af[mt][2], af[mt][3],
                            bf[p][2], bf[p][3]);
                }
        }
    }

#pragma unroll
    for (int mt = 0; mt < 2; mt++) {
        const int row = m0 + wm + mt * 16 + tr;
#pragma unroll
        for (int nt = 0; nt < 8; nt++) {
            const int col = n0 + wn + nt * 8 + tc * 2;
            const float bv0 = __ldg(&bias[col]), bv1 = __ldg(&bias[col + 1]);
            *(float2*)&Cf[(size_t)row * DDIM + col] =
                make_float2(acc[mt][nt][0] + bv0, acc[mt][nt][1] + bv1);
            *(float2*)&Cf[(size_t)(row + 8) * DDIM + col] =
                make_float2(acc[mt][nt][2] + bv0, acc[mt][nt][3] + bv1);
        }
    }
}

// ---------------- KV = K^T V via smem-transpose + fp16 mma ----------------
#define TSTRIDE 40

__global__ __launch_bounds__(256)
void kv_mma2_kernel()
{
    __shared__ __half Kt[64 * TSTRIDE];
    __shared__ __half Vt[64 * TSTRIDE];
    const uint32_t kt_u = smem_u32(Kt), vt_u = smem_u32(Vt);

    const int bh = blockIdx.x, part = blockIdx.y;
    const int b = bh >> 4, h = bh & 15;
    const int sbeg = part * (SSEQ / NPART);   // 256 s per part

    const __half* Kp = g_QKVh[1] + (size_t)b * SSEQ * DDIM + h * DK;
    const __half* Vp = g_QKVh[2] + (size_t)b * SSEQ * DDIM + h * DK;

    const int tid = threadIdx.x;
    const int wid = tid >> 5, lane = tid & 31;
    const int ls = tid & 31;
    const int d0 = (tid >> 5) * 8;
    const int wm = (wid & 3) * 16;
    const int wn = (wid >> 2) * 32;

    float acc[4][4];
#pragma unroll
    for (int n = 0; n < 4; n++)
#pragma unroll
        for (int q = 0; q < 4; q++) acc[n][q] = 0.f;
    float ksp[8];
#pragma unroll
    for (int j = 0; j < 8; j++) ksp[j] = 0.f;

#pragma unroll 1
    for (int t = 0; t < 8; t++) {
        const int s0 = sbeg + t * 32;
        uint4 k8 = *(const uint4*)&Kp[(size_t)(s0 + ls) * DDIM + d0];
        uint4 v8 = *(const uint4*)&Vp[(size_t)(s0 + ls) * DDIM + d0];
        const __half* kh = (const __half*)&k8;
        const __half* vh = (const __half*)&v8;
#pragma unroll
        for (int j = 0; j < 8; j++) {
            Kt[(d0 + j) * TSTRIDE + ls] = kh[j];
            Vt[(d0 + j) * TSTRIDE + ls] = vh[j];
            ksp[j] += __half2float(kh[j]);
        }
        __syncthreads();

#pragma unroll
        for (int kk = 0; kk < 2; kk++) {
            uint32_t af[4];
            {
                const int r = lane & 15, sel = lane >> 4;
                const int row = wm + r;
                ldm_x4(af, kt_u + (uint32_t)((row * TSTRIDE + (kk * 2 + sel) * 8) * 2));
            }
            uint32_t bf[2][4];
            {
                const int g = lane >> 3, rr = lane & 7;
#pragma unroll
                for (int p = 0; p < 2; p++) {
                    const int row = wn + p * 16 + (g >> 1) * 8 + rr;
                    ldm_x4(bf[p], vt_u + (uint32_t)((row * TSTRIDE + (kk * 2 + (g & 1)) * 8) * 2));
                }
            }
#pragma unroll
            for (int p = 0; p < 2; p++) {
                mma_f16(acc[2*p][0], acc[2*p][1], acc[2*p][2], acc[2*p][3],
                        af[0], af[1], af[2], af[3], bf[p][0], bf[p][1]);
                mma_f16(acc[2*p+1][0], acc[2*p+1][1], acc[2*p+1][2], acc[2*p+1][3],
                        af[0], af[1], af[2], af[3], bf[p][2], bf[p][3]);
            }
        }
        __syncthreads();
    }

    const int tr = lane >> 2, tc = lane & 3;
    float* out = g_KVp[part] + (size_t)bh * DK * DK;
#pragma unroll
    for (int nt = 0; nt < 4; nt++) {
        const int e = wn + nt * 8 + tc * 2;
        *(float2*)&out[(wm + tr) * DK + e]     = make_float2(acc[nt][0], acc[nt][1]);
        *(float2*)&out[(wm + tr + 8) * DK + e] = make_float2(acc[nt][2], acc[nt][3]);
    }
#pragma unroll
    for (int j = 0; j < 8; j++) {
#pragma unroll
        for (int off = 16; off > 0; off >>= 1)
            ksp[j] += __shfl_xor_sync(0xFFFFFFFF, ksp[j], off);
    }
    if (lane == 0) {
#pragma unroll
        for (int j = 0; j < 8; j++)
            g_Ksp[part][bh * DK + d0 + j] = ksp[j];
    }
}

// ---------------- reduce partials -> KVh (transposed [e][d], fp16) + Ksum fp32 ----------------
__global__ __launch_bounds__(256)
void kv_reduce_kernel()
{
    const int bh = blockIdx.x;
    const int tid = threadIdx.x;
    const size_t base = (size_t)bh * DK * DK;
    for (int i = tid; i < DK * DK; i += 256) {
        float s = 0.f;
#pragma unroll
        for (int p = 0; p < NPART; p++) s += g_KVp[p][base + i];
        const int d = i >> 6, e = i & 63;
        g_KVh[base + (size_t)e * DK + d] = __float2half_rn(s);
    }
    if (tid < DK) {
        const int o = bh * DK + tid;
        float s = 0.f;
#pragma unroll
        for (int p = 0; p < NPART; p++) s += g_Ksp[p][o];
        g_Ksum[o] = s;
    }
}

// ---------------- attn: out = (Q·KV)/(Q·Ksum+eps) via fp16 mma ----------------
__global__ __launch_bounds__(256)
void attn_mma_kernel()
{
    __shared__ char qsm[128 * 128];
    __shared__ char kvsm[64 * 128];
    __shared__ float Ksm[DK];
    __shared__ float zs[128];
    const uint32_t q_u = smem_u32(qsm);
    const uint32_t kv_u = smem_u32(kvsm);

    const int bh = blockIdx.y;
    const int b = bh >> 4, h = bh & 15;
    const int s_base = blockIdx.x * 128;

    const __half* Qp  = g_QKVh[0] + (size_t)b * SSEQ * DDIM + h * DK;
    const __half* KVp = g_KVh + (size_t)bh * DK * DK;
    __half* Op        = g_Ah + (size_t)b * SSEQ * DDIM + h * DK;

    const int tid = threadIdx.x;
    const int wid = tid >> 5, lane = tid & 31;

#pragma unroll
    for (int i = 0; i < 4; i++) {
        int idx = tid + i * 256;
        int r = idx >> 3, c = idx & 7;
        int cs = c ^ (r & 7);
        cp16(q_u + (uint32_t)(r * 128 + cs * 16),
             &Qp[(size_t)(s_base + r) * DDIM + c * 8]);
    }
#pragma unroll
    for (int i = 0; i < 2; i++) {
        int idx = tid + i * 256;
        int r = idx >> 3, c = idx & 7;
        int cs = c ^ (r & 7);
        cp16(kv_u + (uint32_t)(r * 128 + cs * 16), &KVp[(size_t)r * DK + c * 8]);
    }
    if (tid < DK) Ksm[tid] = g_Ksum[bh * DK + tid];
    asm volatile("cp.async.commit_group;" ::: "memory");
    asm volatile("cp.async.wait_group 0;" ::: "memory");
    __syncthreads();

    if (tid < 128) {
        const int r = tid;
        float z = 0.f;
#pragma unroll
        for (int d = 0; d < DK; d++) {
            __half hv = *(const __half*)(qsm + r * 128 + (((d >> 3) ^ (r & 7)) * 16) + (d & 7) * 2);
            z += __half2float(hv) * Ksm[d];
        }
        zs[r] = 1.f / (z + 1e-6f);
    }

    const int wm = wid * 16;
    float acc[8][4];
#pragma unroll
    for (int j = 0; j < 8; j++)
#pragma unroll
        for (int q = 0; q < 4; q++) acc[j][q] = 0.f;

#pragma unroll
    for (int ks = 0; ks < 4; ks++) {
        uint32_t af[4];
        {
            const int r = lane & 15, sel = lane >> 4;
            const int row = wm + r;
            const int ch = (ks * 2 + sel) ^ (row & 7);
            ldm_x4(af, q_u + row * 128 + ch * 16);
        }
        uint32_t bf[4][4];
        {
            const int g = lane >> 3, rr = lane & 7;
#pragma unroll
            for (int p = 0; p < 4; p++) {
                const int row = p * 16 + (g >> 1) * 8 + rr;
                const int ch = (ks * 2 + (g & 1)) ^ (row & 7);
                ldm_x4(bf[p], kv_u + row * 128 + ch * 16);
            }
        }
#pragma unroll
        for (int p = 0; p < 4; p++) {
            mma_f16(acc[2*p][0], acc[2*p][1], acc[2*p][2], acc[2*p][3],
                    af[0], af[1], af[2], af[3], bf[p][0], bf[p][1]);
            mma_f16(acc[2*p+1][0], acc[2*p+1][1], acc[2*p+1][2], acc[2*p+1][3],
                    af[0], af[1], af[2], af[3], bf[p][2], bf[p][3]);
        }
    }
    __syncthreads();

    const int tr = lane >> 2, tc = lane & 3;
    const float iz0 = zs[wm + tr], iz1 = zs[wm + tr + 8];
#pragma unroll
    for (int nt = 0; nt < 8; nt++) {
        const int e = nt * 8 + tc * 2;
        __half2 o0 = __floats2half2_rn(acc[nt][0] * iz0, acc[nt][1] * iz0);
        __half2 o1 = __floats2half2_rn(acc[nt][2] * iz1, acc[nt][3] * iz1);
        *(__half2*)&Op[(size_t)(s_base + wm + tr) * DDIM + e]     = o0;
        *(__half2*)&Op[(size_t)(s_base + wm + tr + 8) * DDIM + e] = o1;
    }
}

// ---------------- host ----------------
extern "C" void kernel_launch(void* const* d_in, const int* in_sizes, int n_in,
                              void* d_out, int out_size)
{
    const float* x  = (const float*)d_in[0];
    const float* Wq = (const float*)d_in[1];
    const float* bq = (const float*)d_in[2];
    const float* Wk = (const float*)d_in[3];
    const float* bk = (const float*)d_in[4];
    const float* Wv = (const float*)d_in[5];
    const float* bv = (const float*)d_in[6];
    const float* Wo = (const float*)d_in[7];
    const float* bo = (const float*)d_in[8];

    __half *Xh, *QKVh, *Ah, *Wh;
    float* b3;
    cudaGetSymbolAddress((void**)&Xh, g_Xh);
    cudaGetSymbolAddress((void**)&QKVh, g_QKVh);
    cudaGetSymbolAddress((void**)&Ah, g_Ah);
    cudaGetSymbolAddress((void**)&Wh, g_Wh);
    cudaGetSymbolAddress((void**)&b3, g_b3);

    __half* Who = Wh + 3 * (size_t)DDIM * DDIM;

    cudaFuncSetAttribute(gemm_qkv, cudaFuncAttributeMaxDynamicSharedMemorySize, GEMM_SMEM);
    cudaFuncSetAttribute(gemm_h,   cudaFuncAttributeMaxDynamicSharedMemorySize, GEMM_SMEM);

    f2h_all_kernel<<<NXB + 4 * NWB, F2H_TPB>>>(x, Wq, Wk, Wv, Wo, Xh, Wh);
    cudaMemcpyAsync(b3,            bq, DDIM * sizeof(float), cudaMemcpyDeviceToDevice);
    cudaMemcpyAsync(b3 + DDIM,     bk, DDIM * sizeof(float), cudaMemcpyDeviceToDevice);
    cudaMemcpyAsync(b3 + 2 * DDIM, bv, DDIM * sizeof(float), cudaMemcpyDeviceToDevice);

    gemm_qkv<<<dim3(3 * DDIM / BNg, MTOT / BMg), 256, GEMM_SMEM>>>(Xh, Wh, b3, QKVh);

    kv_mma2_kernel<<<dim3(BB * HH, NPART), 256>>>();
    kv_reduce_kernel<<<BB * HH, 256>>>();
    attn_mma_kernel<<<dim3(SSEQ / 128, BB * HH), 256>>>();

    gemm_h<<<dim3(DDIM / BNg, MTOT / BMg), 256, GEMM_SMEM>>>(Ah, Who, bo, (float*)d_out);
}